// round 14
// baseline (speedup 1.0000x reference)
#include <cuda_runtime.h>
#include <math.h>

typedef unsigned long long ull;

// ---------------- problem constants ----------------
#define RAYS    1024
#define NCO     64
#define NFI     32
#define NAGG    96
#define MIND    0.035f
#define MAXD    35.0f
#define DD      90
#define NHEADS  12
#define DHD     64
#define INNERD  768
#define MLPD    1536
#define KVD     768
#define PTOK    128
#define LDH     100     // paired row stride 2*LDH=200 (== 8 mod 32 -> conflict-free)
#define LDSS    132     // paired row stride 2*LDSS=264 (== 8 mod 32)
#define PPB     16      // points per block (2 warps x 8 points = 4 pairs/warp)

// ---------------- device scratch ----------------
__device__ float g_kt   [2*NHEADS*DHD*PTOK];   // [layer][head][d][key], PRE-SCALED by 0.125
__device__ float g_vv   [2*NHEADS*PTOK*DHD];   // [layer][head][key][d]
__device__ float g_dens_c[RAYS*NCO];
__device__ float g_col_c [RAYS*NCO*3];
__device__ float g_dens_f[RAYS*NAGG];
__device__ float g_col_f [RAYS*NAGG*3];
__device__ float g_depths[RAYS*NAGG];
// LN-folded weights: W' = diag(ln_w) @ W ; U = colsum(diag(ln_w)@W) ; C = ln_b @ W (+bias)
__device__ float g_wq2[2*DD*INNERD];
__device__ float g_uq [2*INNERD];
__device__ float g_cq [2*INNERD];
__device__ float g_w12[2*DD*MLPD];
__device__ float g_u1 [2*MLPD];
__device__ float g_c1 [2*MLPD];   // includes b1

struct NetP {
    const float *x, *rays;
    const float *wo, *bo, *w2, *b2;
    const float *wc1, *bc1, *wc2, *bc2, *wd1, *bd1, *wd2, *bd2;
};

__device__ __forceinline__ float coarse_depth(int s) {
    const float step = (MAXD - MIND) / 64.0f;
    return 0.5f * ((MIND + s * step) + (MIND + (s + 1) * step));
}

// ---------------- f32x2 helpers ----------------
__device__ __forceinline__ ull pack2(float x, float y) {
    ull r; asm("mov.b64 %0, {%1, %2};" : "=l"(r) : "f"(x), "f"(y)); return r;
}
__device__ __forceinline__ ull pack2d(float x) { return pack2(x, x); }
__device__ __forceinline__ void ffma2(ull& d, ull a, ull b) {
    asm("fma.rn.f32x2 %0, %1, %2, %0;" : "+l"(d) : "l"(a), "l"(b));
}
__device__ __forceinline__ float2 unpack2(ull v) {
    float2 r; asm("mov.b64 {%0, %1}, %2;" : "=f"(r.x), "=f"(r.y) : "l"(v)); return r;
}

// paired activation layout: buf[(p>>1)*2*LD + 2*k + (p&1)]
#define PIDX(p, LD, k) (((p) >> 1) * (2 * (LD)) + 2 * (k) + ((p) & 1))

// ---------------- KV precompute ----------------
__global__ void kv_kernel(const float* __restrict__ z, const float* __restrict__ wkv) {
    int e = blockIdx.x * blockDim.x + threadIdx.x;
    if (e >= 2 * PTOK * 2 * INNERD) return;
    int layer = e / (PTOK * 2 * INNERD);
    int rem   = e - layer * (PTOK * 2 * INNERD);
    int p   = rem / (2 * INNERD);
    int col = rem - p * (2 * INNERD);
    const float* zr = z + p * KVD;
    const float* wc = wkv + layer * KVD * 2 * INNERD + col;
    float acc = 0.f;
#pragma unroll 8
    for (int k = 0; k < KVD; k++) acc = fmaf(zr[k], wc[k * 2 * INNERD], acc);
    int head = col >> 7, c = col & 127;
    // 0.125 = DH^-0.5 folded into K^T (power of two -> exact)
    if (c < DHD) g_kt[((layer * NHEADS + head) * DHD + c) * PTOK + p] = acc * 0.125f;
    else         g_vv[((layer * NHEADS + head) * PTOK + p) * DHD + (c - DHD)] = acc;
}

// ---------------- LN-fold precompute ----------------
__global__ void fold_scale_kernel(const float* __restrict__ ln1w, const float* __restrict__ wq,
                                  const float* __restrict__ ln2w, const float* __restrict__ w1) {
    int e = blockIdx.x * blockDim.x + threadIdx.x;
    const int T1 = 2 * DD * INNERD;
    if (e < T1) {
        int layer = e / (DD * INNERD);
        int k = (e - layer * DD * INNERD) / INNERD;
        g_wq2[e] = ln1w[layer * DD + k] * wq[e];
    } else if (e < T1 + 2 * DD * MLPD) {
        int e2 = e - T1;
        int layer = e2 / (DD * MLPD);
        int k = (e2 - layer * DD * MLPD) / MLPD;
        g_w12[e2] = ln2w[layer * DD + k] * w1[e2];
    }
}

__global__ void fold_uc_kernel(const float* __restrict__ ln1w, const float* __restrict__ ln1b,
                               const float* __restrict__ wq,
                               const float* __restrict__ ln2w, const float* __restrict__ ln2b,
                               const float* __restrict__ w1, const float* __restrict__ b1) {
    int e = blockIdx.x * blockDim.x + threadIdx.x;
    if (e < 2 * INNERD) {
        int layer = e / INNERD, o = e - layer * INNERD;
        const float* W = wq + layer * DD * INNERD + o;
        float U = 0.f, C = 0.f;
        for (int k = 0; k < DD; k++) {
            float w = W[k * INNERD];
            U = fmaf(ln1w[layer * DD + k], w, U);
            C = fmaf(ln1b[layer * DD + k], w, C);
        }
        g_uq[e] = U; g_cq[e] = C;
    } else if (e < 2 * INNERD + 2 * MLPD) {
        int e2 = e - 2 * INNERD;
        int layer = e2 / MLPD, o = e2 - layer * MLPD;
        const float* W = w1 + layer * DD * MLPD + o;
        float U = 0.f, C = 0.f;
        for (int k = 0; k < DD; k++) {
            float w = W[k * MLPD];
            U = fmaf(ln2w[layer * DD + k], w, U);
            C = fmaf(ln2b[layer * DD + k], w, C);
        }
        g_u1[e2] = U; g_c1[e2] = C + b1[e2];
    }
}

// ---------------- FFMA2 register-tiled GEMM (simple, R3-best) --------------
// Input is PAIRED smem. Warp owns 4 point-pairs (8 points). Lane owns:
//   WMODE==1 (vector weights): cols NCOL*l + j  (NCOL in {2,4}), NO == 32*NCOL
//   WMODE==0 (strided):        cols l + 32*j, masked at NO
template <int NI, int NCOL, int LDIN, int WMODE, int NO, class Epi>
__device__ __forceinline__ void gemm2(const float* __restrict__ in,
                                      const float* __restrict__ W,
                                      const int ldw, Epi epi) {
    const int l  = threadIdx.x & 31;
    const int wp = threadIdx.x >> 5;
    ull acc[4][NCOL];
#pragma unroll
    for (int i = 0; i < 4; i++)
#pragma unroll
        for (int j = 0; j < NCOL; j++) acc[i][j] = 0ull;

    const float* inb = in + (wp * 4) * (2 * LDIN);
    int ni = 0;
#pragma unroll 2
    for (; ni + 4 <= NI; ni += 4) {
        ull a[4][4];
#pragma unroll
        for (int i = 0; i < 4; i++) {
            ulonglong2 t0 = *reinterpret_cast<const ulonglong2*>(inb + i * 2 * LDIN + 2 * ni);
            ulonglong2 t1 = *reinterpret_cast<const ulonglong2*>(inb + i * 2 * LDIN + 2 * ni + 4);
            a[i][0] = t0.x; a[i][1] = t0.y; a[i][2] = t1.x; a[i][3] = t1.y;
        }
#pragma unroll
        for (int k = 0; k < 4; k++) {
            ull wv[NCOL];
            if (WMODE == 1) {
                if (NCOL == 4) {
                    float4 w4 = *reinterpret_cast<const float4*>(W + (ni + k) * ldw + 4 * l);
                    wv[0] = pack2d(w4.x); wv[1] = pack2d(w4.y);
                    wv[2] = pack2d(w4.z); wv[3] = pack2d(w4.w);
                } else {
                    float2 w2 = *reinterpret_cast<const float2*>(W + (ni + k) * ldw + 2 * l);
                    wv[0] = pack2d(w2.x); wv[1] = pack2d(w2.y);
                }
            } else {
#pragma unroll
                for (int j = 0; j < NCOL; j++) {
                    int o = l + 32 * j;
                    float w = (o < NO) ? W[(ni + k) * ldw + o] : 0.f;
                    wv[j] = pack2d(w);
                }
            }
#pragma unroll
            for (int i = 0; i < 4; i++)
#pragma unroll
                for (int j = 0; j < NCOL; j++) ffma2(acc[i][j], a[i][k], wv[j]);
        }
    }
    if (NI & 2) {   // remainder of 2 (NI=90)
        ull a[4][2];
#pragma unroll
        for (int i = 0; i < 4; i++) {
            ulonglong2 t0 = *reinterpret_cast<const ulonglong2*>(inb + i * 2 * LDIN + 2 * ni);
            a[i][0] = t0.x; a[i][1] = t0.y;
        }
#pragma unroll
        for (int k = 0; k < 2; k++) {
            ull wv[NCOL];
            if (WMODE == 1) {
                if (NCOL == 4) {
                    float4 w4 = *reinterpret_cast<const float4*>(W + (ni + k) * ldw + 4 * l);
                    wv[0] = pack2d(w4.x); wv[1] = pack2d(w4.y);
                    wv[2] = pack2d(w4.z); wv[3] = pack2d(w4.w);
                } else {
                    float2 w2 = *reinterpret_cast<const float2*>(W + (ni + k) * ldw + 2 * l);
                    wv[0] = pack2d(w2.x); wv[1] = pack2d(w2.y);
                }
            } else {
#pragma unroll
                for (int j = 0; j < NCOL; j++) {
                    int o = l + 32 * j;
                    float w = (o < NO) ? W[(ni + k) * ldw + o] : 0.f;
                    wv[j] = pack2d(w);
                }
            }
#pragma unroll
            for (int i = 0; i < 4; i++)
#pragma unroll
                for (int j = 0; j < NCOL; j++) ffma2(acc[i][j], a[i][k], wv[j]);
        }
    }
#pragma unroll
    for (int i = 0; i < 4; i++)
#pragma unroll
        for (int j = 0; j < NCOL; j++) {
            int o = (WMODE == 1) ? (NCOL * l + j) : (l + 32 * j);
            if (WMODE == 1 || o < NO) epi(wp * 4 + i, o, unpack2(acc[i][j]));
        }
}

// Warp-local LN statistics only (mean, rsqrt(var)) -> st[2*pt], st[2*pt+1]
__device__ __forceinline__ void ln_stats(const float* __restrict__ src, float* __restrict__ st) {
    const int l  = threadIdx.x & 31;
    const int wp = threadIdx.x >> 5;
    const int pl = l >> 2, sub = l & 3;
    const int pt = wp * 8 + pl;
    const float* rowb = src + ((pt >> 1) * (2 * LDH) + (pt & 1));
    float s = 0.f;
    for (int f = sub; f < DD; f += 4) s += rowb[2 * f];
    s += __shfl_xor_sync(0xffffffffu, s, 1);
    s += __shfl_xor_sync(0xffffffffu, s, 2);
    float m = s * (1.0f / DD);
    float v = 0.f;
    for (int f = sub; f < DD; f += 4) { float d = rowb[2 * f] - m; v += d * d; }
    v += __shfl_xor_sync(0xffffffffu, v, 1);
    v += __shfl_xor_sync(0xffffffffu, v, 2);
    float inv = 1.0f / sqrtf(v * (1.0f / DD) + 1e-5f);
    if (sub == 0) { st[2 * pt] = m; st[2 * pt + 1] = inv; }
    __syncwarp();
}

// ---------------- fused NeRF network: 16 points / 2-warp block ----------------
// __launch_bounds__(64, 9): target <=113 regs so 9 blocks (18 warps/SM) stay
// resident; smem 19KB*9 = 171KB fits. Single-variable experiment vs R13.
__global__ void __launch_bounds__(64, 9) net_kernel(NetP P, int mode /*0 coarse, 1 fine*/) {
    __shared__ __align__(16) float sh_h [(PPB / 2) * 2 * LDH ];  // 1600
    __shared__ __align__(16) float sh_s [(PPB / 2) * 2 * LDSS];  // 2112
    __shared__ __align__(16) float sh_qo[(PPB / 2) * 2 * DHD ];  // 1024 (coords/q/o aliased)
    __shared__ float sh_st[2 * PPB];   // (m, inv) per point (LN stats)
    __shared__ float sh_ip[PPB];       // 1/sum_exp per point (softmax)

    const int t  = threadIdx.x;
    const int l  = t & 31;
    const int wp = t >> 5;
    const int pl = l >> 2, sub = l & 3;
    const int base = blockIdx.x * PPB;
    const int S = mode ? NAGG : NCO;

    // ---- coords (temp in sh_qo, consumed by posenc) ----
    if (l < 24) {
        int p = l / 3, d = l - (l / 3) * 3;
        int gp = base + wp * 8 + p;
        int r = gp / S, s = gp - r * S;
        float depth = mode ? g_depths[r * NAGG + s] : coarse_depth(s);
        sh_qo[(wp * 8 + p) * 4 + d] = P.x[r * 3 + d] + P.rays[r * 3 + d] * depth;
    }
    __syncwarp();
    // ---- positional encoding ----
    for (int idx = l; idx < 8 * DD; idx += 32) {
        int p = idx / DD, f = idx - p * DD;
        int bb = (f < 45) ? f : f - 45;
        int dim = bb / 15, oct = bb - dim * 15;
        int pt = wp * 8 + p;
        float arg = sh_qo[pt * 4 + dim] * (3.14159265358979323846f * (float)(1 << oct));
        sh_h[PIDX(pt, LDH, f)] = (f < 45) ? sinf(arg) : cosf(arg);
    }
    __syncwarp();

    for (int layer = 0; layer < 2; layer++) {
        // ---- LN1 stats + attention (LN folded into wq via g_wq2/g_uq/g_cq) ----
        ln_stats(sh_h, sh_st);
        {
            float m_[8], iv_[8];
#pragma unroll
            for (int k = 0; k < 8; k++) {
                m_[k]  = sh_st[2 * (wp * 8 + k)];
                iv_[k] = sh_st[2 * (wp * 8 + k) + 1];
            }
            float2 accw[4][3];
#pragma unroll
            for (int i = 0; i < 4; i++)
#pragma unroll
                for (int j = 0; j < 3; j++) accw[i][j] = make_float2(0.f, 0.f);
            for (int head = 0; head < NHEADS; head++) {
                const float* Uq = g_uq + layer * INNERD + head * DHD;
                const float* Cq = g_cq + layer * INNERD + head * DHD;
                gemm2<DD, 2, LDH, 1, DHD>(sh_h, g_wq2 + layer * DD * INNERD + head * DHD, INNERD,
                    [&](int pr, int o, float2 v) {
                        float U = Uq[o], C = Cq[o];
                        int i2 = (pr & 3) * 2;
                        v.x = iv_[i2]     * (v.x - m_[i2]     * U) + C;
                        v.y = iv_[i2 + 1] * (v.y - m_[i2 + 1] * U) + C;
                        *reinterpret_cast<float2*>(&sh_qo[pr * 2 * DHD + 2 * o]) = v;
                    });
                __syncwarp();
                // q . K^T (K pre-scaled by 0.125 -> plain store epilogue)
                gemm2<DHD, 4, DHD, 1, PTOK>(sh_qo, g_kt + (layer * NHEADS + head) * DHD * PTOK, PTOK,
                    [&](int pr, int o, float2 v) {
                        *reinterpret_cast<float2*>(&sh_s[pr * 2 * LDSS + 2 * o]) = v;
                    });
                __syncwarp();
                // ---- softmax over 128 keys: 4 lanes / point; stores UNNORMALIZED
                // exp, 1/sum folded into att.V epilogue ----
                {
                    const int pt = wp * 8 + pl;
                    float* rowb = sh_s + ((pt >> 1) * 2 * LDSS + (pt & 1));
                    float mx = rowb[2 * sub];
#pragma unroll
                    for (int k = 1; k < 32; k++) mx = fmaxf(mx, rowb[2 * (sub + 4 * k)]);
                    mx = fmaxf(mx, __shfl_xor_sync(0xffffffffu, mx, 1));
                    mx = fmaxf(mx, __shfl_xor_sync(0xffffffffu, mx, 2));
                    float ps = 0.f;
#pragma unroll
                    for (int k = 0; k < 32; k++) {
                        float v = __expf(rowb[2 * (sub + 4 * k)] - mx);
                        rowb[2 * (sub + 4 * k)] = v;
                        ps += v;
                    }
                    ps += __shfl_xor_sync(0xffffffffu, ps, 1);
                    ps += __shfl_xor_sync(0xffffffffu, ps, 2);
                    if (sub == 0) sh_ip[pt] = 1.0f / ps;
                }
                __syncwarp();
                gemm2<PTOK, 2, LDSS, 1, DHD>(sh_s, g_vv + (layer * NHEADS + head) * PTOK * DHD, DHD,
                    [&](int pr, int o, float2 v) {
                        v.x *= sh_ip[2 * pr];
                        v.y *= sh_ip[2 * pr + 1];
                        *reinterpret_cast<float2*>(&sh_qo[pr * 2 * DHD + 2 * o]) = v;
                    });
                __syncwarp();
                gemm2<DHD, 3, DHD, 0, DD>(sh_qo, P.wo + layer * INNERD * DD + head * DHD * DD, DD,
                    [&](int pr, int o, float2 v) {
                        int j = o >> 5, i = pr & 3;
                        accw[i][j].x += v.x; accw[i][j].y += v.y;
                    });
                __syncwarp();
            }
            const float* bo = P.bo + layer * DD;
#pragma unroll
            for (int i = 0; i < 4; i++)
#pragma unroll
                for (int j = 0; j < 3; j++) {
                    int o = l + 32 * j;
                    if (o < DD) {
                        int pr = wp * 4 + i;
                        float2* addr = reinterpret_cast<float2*>(&sh_h[pr * 2 * LDH + 2 * o]);
                        float2 h = *addr;
                        float bb = bo[o];
                        h.x += accw[i][j].x + bb;
                        h.y += accw[i][j].y + bb;
                        *addr = h;
                    }
                }
            __syncwarp();
        }
        // ---- LN2 stats + MLP (LN folded into w1 via g_w12/g_u1/g_c1) ----
        ln_stats(sh_h, sh_st);
        {
            float m_[8], iv_[8];
#pragma unroll
            for (int k = 0; k < 8; k++) {
                m_[k]  = sh_st[2 * (wp * 8 + k)];
                iv_[k] = sh_st[2 * (wp * 8 + k) + 1];
            }
            float2 accm[4][3];
#pragma unroll
            for (int i = 0; i < 4; i++)
#pragma unroll
                for (int j = 0; j < 3; j++) accm[i][j] = make_float2(0.f, 0.f);
            for (int c = 0; c < MLPD / 128; c++) {
                const float* U1 = g_u1 + layer * MLPD + c * 128;
                const float* C1 = g_c1 + layer * MLPD + c * 128;
                gemm2<DD, 4, LDH, 1, 128>(sh_h, g_w12 + layer * DD * MLPD + c * 128, MLPD,
                    [&](int pr, int o, float2 v) {
                        float U = U1[o], C = C1[o];
                        int i2 = (pr & 3) * 2;
                        float x0 = iv_[i2]     * (v.x - m_[i2]     * U) + C;
                        float x1 = iv_[i2 + 1] * (v.y - m_[i2 + 1] * U) + C;
                        v.x = 0.5f * x0 * (1.0f + erff(x0 * 0.70710678118654752f));
                        v.y = 0.5f * x1 * (1.0f + erff(x1 * 0.70710678118654752f));
                        *reinterpret_cast<float2*>(&sh_s[pr * 2 * LDSS + 2 * o]) = v;
                    });
                __syncwarp();
                gemm2<128, 3, LDSS, 0, DD>(sh_s, P.w2 + layer * MLPD * DD + c * 128 * DD, DD,
                    [&](int pr, int o, float2 v) {
                        int j = o >> 5, i = pr & 3;
                        accm[i][j].x += v.x; accm[i][j].y += v.y;
                    });
                __syncwarp();
            }
            const float* b2 = P.b2 + layer * DD;
#pragma unroll
            for (int i = 0; i < 4; i++)
#pragma unroll
                for (int j = 0; j < 3; j++) {
                    int o = l + 32 * j;
                    if (o < DD) {
                        int pr = wp * 4 + i;
                        float2* addr = reinterpret_cast<float2*>(&sh_h[pr * 2 * LDH + 2 * o]);
                        float2 h = *addr;
                        float bb = b2[o];
                        h.x += accm[i][j].x + bb;
                        h.y += accm[i][j].y + bb;
                        *addr = h;
                    }
                }
            __syncwarp();
        }
    }

    // ---- density head ----
    gemm2<DD, 4, LDH, 1, 128>(sh_h, P.wd1, 128,
        [&](int pr, int o, float2 v) {
            float bb = P.bd1[o];
            v.x = fmaxf(v.x + bb, 0.f); v.y = fmaxf(v.y + bb, 0.f);
            *reinterpret_cast<float2*>(&sh_s[pr * 2 * LDSS + 2 * o]) = v;
        });
    __syncwarp();
    {
        const int pt = wp * 8 + pl;
        const float* rowb = sh_s + ((pt >> 1) * 2 * LDSS + (pt & 1));
        float a = 0.f;
#pragma unroll
        for (int k = 0; k < 32; k++) a = fmaf(rowb[2 * (sub + 4 * k)], P.wd2[sub + 4 * k], a);
        a += __shfl_xor_sync(0xffffffffu, a, 1);
        a += __shfl_xor_sync(0xffffffffu, a, 2);
        if (sub == 0) {
            a += P.bd2[0];
            float sp = fmaxf(a, 0.f) + log1pf(__expf(-fabsf(a)));
            float* dst = mode ? g_dens_f : g_dens_c;
            dst[base + pt] = sp;
        }
    }
    __syncwarp();
    // ---- color head ----
    gemm2<DD, 4, LDH, 1, 128>(sh_h, P.wc1, 128,
        [&](int pr, int o, float2 v) {
            float bb = P.bc1[o];
            v.x = fmaxf(v.x + bb, 0.f); v.y = fmaxf(v.y + bb, 0.f);
            *reinterpret_cast<float2*>(&sh_s[pr * 2 * LDSS + 2 * o]) = v;
        });
    __syncwarp();
    {
        const int pt = wp * 8 + pl;
        const float* rowb = sh_s + ((pt >> 1) * 2 * LDSS + (pt & 1));
        float c0 = 0.f, c1 = 0.f, c2 = 0.f;
#pragma unroll
        for (int k = 0; k < 32; k++) {
            float v = rowb[2 * (sub + 4 * k)];
            const float* wr = P.wc2 + (sub + 4 * k) * 3;
            c0 = fmaf(v, wr[0], c0);
            c1 = fmaf(v, wr[1], c1);
            c2 = fmaf(v, wr[2], c2);
        }
        c0 += __shfl_xor_sync(0xffffffffu, c0, 1);
        c0 += __shfl_xor_sync(0xffffffffu, c0, 2);
        c1 += __shfl_xor_sync(0xffffffffu, c1, 1);
        c1 += __shfl_xor_sync(0xffffffffu, c1, 2);
        c2 += __shfl_xor_sync(0xffffffffu, c2, 1);
        c2 += __shfl_xor_sync(0xffffffffu, c2, 2);
        if (sub == 0) {
            int gp = base + pt;
            float* dst = mode ? g_col_f : g_col_c;
            dst[gp * 3 + 0] = 1.0f / (1.0f + __expf(-(c0 + P.bc2[0])));
            dst[gp * 3 + 1] = 1.0f / (1.0f + __expf(-(c1 + P.bc2[1])));
            dst[gp * 3 + 2] = 1.0f / (1.0f + __expf(-(c2 + P.bc2[2])));
        }
    }
}

// ---------------- coarse render + PDF resampling + merge ----------------
__global__ void coarse_post_kernel(float* __restrict__ out) {
    int r = blockIdx.x * blockDim.x + threadIdx.x;
    if (r >= RAYS) return;
    float cd[NCO];
    for (int s = 0; s < NCO; s++) cd[s] = coarse_depth(s);

    float w[NCO];
    float T = 1.f, acc = 0.f, rgb0 = 0.f, rgb1 = 0.f, rgb2 = 0.f, dsum = 0.f;
    for (int s = 0; s < NCO; s++) {
        float seg = (s < NCO - 1) ? cd[s + 1] - cd[s] : 1e10f;
        float dens = g_dens_c[r * NCO + s];
        float alpha = 1.0f - expf(-dens * seg);
        float wi = alpha * T;
        w[s] = wi;
        T *= (1.0f - alpha + 1e-10f);
        acc += wi;
        rgb0 += wi * g_col_c[(r * NCO + s) * 3 + 0];
        rgb1 += wi * g_col_c[(r * NCO + s) * 3 + 1];
        rgb2 += wi * g_col_c[(r * NCO + s) * 3 + 2];
        dsum += wi * cd[s];
    }
    float inv = 1.0f / (acc + 1e-8f);
    out[3072 + r * 3 + 0] = 1.0f - acc + (rgb0 * inv) * acc;
    out[3072 + r * 3 + 1] = 1.0f - acc + (rgb1 * inv) * acc;
    out[3072 + r * 3 + 2] = 1.0f - acc + (rgb2 * inv) * acc;
    out[7168 + r] = dsum * inv;

    float bins[63], cdf[63];
    for (int i = 0; i < 63; i++) bins[i] = 0.5f * (cd[i] + cd[i + 1]);
    float wsum = 0.f;
    for (int i = 0; i < 62; i++) wsum += w[i + 1] + 1e-5f;
    cdf[0] = 0.f;
    float c0 = 0.f;
    for (int i = 0; i < 62; i++) { c0 += (w[i + 1] + 1e-5f) / wsum; cdf[i + 1] = c0; }

    float fd[NFI];
    for (int j = 0; j < NFI; j++) {
        float u = (j + 0.5f) * (1.0f / NFI);
        int ind = 0;
        for (int k = 0; k < 63; k++) if (cdf[k] <= u) ind = k + 1;
        int below = ind - 1; if (below < 0) below = 0; if (below > 62) below = 62;
        int above = ind;     if (above > 62) above = 62;
        float cb = cdf[below], ca = cdf[above];
        float bb = bins[below], ba = bins[above];
        float denom = ca - cb;
        if (denom < 1e-5f) denom = 1.0f;
        fd[j] = bb + (u - cb) / denom * (ba - bb);
    }
    int i = 0, j = 0;
    for (int k = 0; k < NAGG; k++) {
        float v;
        if (j >= NFI || (i < NCO && cd[i] <= fd[j])) v = cd[i++];
        else v = fd[j++];
        g_depths[r * NAGG + k] = v;
    }
}

// ---------------- fine render ----------------
__global__ void fine_post_kernel(float* __restrict__ out) {
    int r = blockIdx.x * blockDim.x + threadIdx.x;
    if (r >= RAYS) return;
    float d[NAGG];
    for (int s = 0; s < NAGG; s++) d[s] = g_depths[r * NAGG + s];
    float T = 1.f, acc = 0.f, rgb0 = 0.f, rgb1 = 0.f, rgb2 = 0.f, dsum = 0.f;
    for (int s = 0; s < NAGG; s++) {
        float seg = (s < NAGG - 1) ? d[s + 1] - d[s] : 1e10f;
        float dens = g_dens_f[r * NAGG + s];
        float alpha = 1.0f - expf(-dens * seg);
        float wi = alpha * T;
        T *= (1.0f - alpha + 1e-10f);
        acc += wi;
        rgb0 += wi * g_col_f[(r * NAGG + s) * 3 + 0];
        rgb1 += wi * g_col_f[(r * NAGG + s) * 3 + 1];
        rgb2 += wi * g_col_f[(r * NAGG + s) * 3 + 2];
        dsum += wi * d[s];
    }
    float inv = 1.0f / (acc + 1e-8f);
    out[r * 3 + 0] = 1.0f - acc + (rgb0 * inv) * acc;
    out[r * 3 + 1] = 1.0f - acc + (rgb1 * inv) * acc;
    out[r * 3 + 2] = 1.0f - acc + (rgb2 * inv) * acc;
    out[6144 + r] = dsum * inv;
}

// ---------------- launch ----------------
extern "C" void kernel_launch(void* const* d_in, const int* in_sizes, int n_in,
                              void* d_out, int out_size) {
    const float* z    = (const float*)d_in[0];
    NetP P;
    P.x    = (const float*)d_in[1];
    P.rays = (const float*)d_in[2];
    const float* ln1w = (const float*)d_in[3];
    const float* ln1b = (const float*)d_in[4];
    const float* wq   = (const float*)d_in[5];
    const float* wkv  = (const float*)d_in[6];
    P.wo   = (const float*)d_in[7];
    P.bo   = (const float*)d_in[8];
    const float* ln2w = (const float*)d_in[9];
    const float* ln2b = (const float*)d_in[10];
    const float* w1   = (const float*)d_in[11];
    const float* b1   = (const float*)d_in[12];
    P.w2   = (const float*)d_in[13];
    P.b2   = (const float*)d_in[14];
    P.wc1  = (const float*)d_in[15];
    P.bc1  = (const float*)d_in[16];
    P.wc2  = (const float*)d_in[17];
    P.bc2  = (const float*)d_in[18];
    P.wd1  = (const float*)d_in[19];
    P.bd1  = (const float*)d_in[20];
    P.wd2  = (const float*)d_in[21];
    P.bd2  = (const float*)d_in[22];
    float* out = (float*)d_out;

    const int FOLD_N = 2 * DD * INNERD + 2 * DD * MLPD;
    kv_kernel<<<(2 * PTOK * 2 * INNERD + 255) / 256, 256>>>(z, wkv);
    fold_scale_kernel<<<(FOLD_N + 255) / 256, 256>>>(ln1w, wq, ln2w, w1);
    fold_uc_kernel<<<(2 * INNERD + 2 * MLPD + 255) / 256, 256>>>(ln1w, ln1b, wq, ln2w, ln2b, w1, b1);
    net_kernel<<<(RAYS * NCO) / PPB, 64>>>(P, 0);
    coarse_post_kernel<<<(RAYS + 127) / 128, 128>>>(out);
    net_kernel<<<(RAYS * NAGG) / PPB, 64>>>(P, 1);
    fine_post_kernel<<<(RAYS + 127) / 128, 128>>>(out);
}

// round 15
// speedup vs baseline: 1.0770x; 1.0770x over previous
#include <cuda_runtime.h>
#include <math.h>

typedef unsigned long long ull;

// ---------------- problem constants ----------------
#define RAYS    1024
#define NCO     64
#define NFI     32
#define NAGG    96
#define MIND    0.035f
#define MAXD    35.0f
#define DD      90
#define NHEADS  12
#define DHD     64
#define INNERD  768
#define MLPD    1536
#define KVD     768
#define PTOK    128
#define LDH     100     // paired row stride 2*LDH=200 (== 8 mod 32 -> conflict-free)
#define LDSS    132     // paired row stride 2*LDSS=264 (== 8 mod 32)
#define PPB     16      // points per block (2 warps x 8 points = 4 pairs/warp)

// ---------------- device scratch ----------------
__device__ float g_kt   [2*NHEADS*DHD*PTOK];   // [layer][head][d][key]
__device__ float g_vv   [2*NHEADS*PTOK*DHD];   // [layer][head][key][d]
__device__ float g_dens_c[RAYS*NCO];
__device__ float g_col_c [RAYS*NCO*3];
__device__ float g_dens_f[RAYS*NAGG];
__device__ float g_col_f [RAYS*NAGG*3];
__device__ float g_depths[RAYS*NAGG];
// LN-folded weights: W' = diag(ln_w) @ W ; U = colsum(diag(ln_w)@W) ; C = ln_b @ W (+bias)
__device__ float g_wq2[2*DD*INNERD];
__device__ float g_uq [2*INNERD];
__device__ float g_cq [2*INNERD];
__device__ float g_w12[2*DD*MLPD];
__device__ float g_u1 [2*MLPD];
__device__ float g_c1 [2*MLPD];   // includes b1

struct NetP {
    const float *x, *rays;
    const float *wo, *bo, *w2, *b2;
    const float *wc1, *bc1, *wc2, *bc2, *wd1, *bd1, *wd2, *bd2;
};

__device__ __forceinline__ float coarse_depth(int s) {
    const float step = (MAXD - MIND) / 64.0f;
    return 0.5f * ((MIND + s * step) + (MIND + (s + 1) * step));
}

// ---------------- f32x2 helpers ----------------
__device__ __forceinline__ ull pack2(float x, float y) {
    ull r; asm("mov.b64 %0, {%1, %2};" : "=l"(r) : "f"(x), "f"(y)); return r;
}
__device__ __forceinline__ ull pack2d(float x) { return pack2(x, x); }
__device__ __forceinline__ void ffma2(ull& d, ull a, ull b) {
    asm("fma.rn.f32x2 %0, %1, %2, %0;" : "+l"(d) : "l"(a), "l"(b));
}
__device__ __forceinline__ float2 unpack2(ull v) {
    float2 r; asm("mov.b64 {%0, %1}, %2;" : "=f"(r.x), "=f"(r.y) : "l"(v)); return r;
}

// paired activation layout: buf[(p>>1)*2*LD + 2*k + (p&1)]
#define PIDX(p, LD, k) (((p) >> 1) * (2 * (LD)) + 2 * (k) + ((p) & 1))

// ---------------- KV precompute ----------------
__global__ void kv_kernel(const float* __restrict__ z, const float* __restrict__ wkv) {
    int e = blockIdx.x * blockDim.x + threadIdx.x;
    if (e >= 2 * PTOK * 2 * INNERD) return;
    int layer = e / (PTOK * 2 * INNERD);
    int rem   = e - layer * (PTOK * 2 * INNERD);
    int p   = rem / (2 * INNERD);
    int col = rem - p * (2 * INNERD);
    const float* zr = z + p * KVD;
    const float* wc = wkv + layer * KVD * 2 * INNERD + col;
    float acc = 0.f;
#pragma unroll 8
    for (int k = 0; k < KVD; k++) acc = fmaf(zr[k], wc[k * 2 * INNERD], acc);
    int head = col >> 7, c = col & 127;
    if (c < DHD) g_kt[((layer * NHEADS + head) * DHD + c) * PTOK + p] = acc;
    else         g_vv[((layer * NHEADS + head) * PTOK + p) * DHD + (c - DHD)] = acc;
}

// ---------------- LN-fold precompute ----------------
__global__ void fold_scale_kernel(const float* __restrict__ ln1w, const float* __restrict__ wq,
                                  const float* __restrict__ ln2w, const float* __restrict__ w1) {
    int e = blockIdx.x * blockDim.x + threadIdx.x;
    const int T1 = 2 * DD * INNERD;
    if (e < T1) {
        int layer = e / (DD * INNERD);
        int k = (e - layer * DD * INNERD) / INNERD;
        g_wq2[e] = ln1w[layer * DD + k] * wq[e];
    } else if (e < T1 + 2 * DD * MLPD) {
        int e2 = e - T1;
        int layer = e2 / (DD * MLPD);
        int k = (e2 - layer * DD * MLPD) / MLPD;
        g_w12[e2] = ln2w[layer * DD + k] * w1[e2];
    }
}

__global__ void fold_uc_kernel(const float* __restrict__ ln1w, const float* __restrict__ ln1b,
                               const float* __restrict__ wq,
                               const float* __restrict__ ln2w, const float* __restrict__ ln2b,
                               const float* __restrict__ w1, const float* __restrict__ b1) {
    int e = blockIdx.x * blockDim.x + threadIdx.x;
    if (e < 2 * INNERD) {
        int layer = e / INNERD, o = e - layer * INNERD;
        const float* W = wq + layer * DD * INNERD + o;
        float U = 0.f, C = 0.f;
        for (int k = 0; k < DD; k++) {
            float w = W[k * INNERD];
            U = fmaf(ln1w[layer * DD + k], w, U);
            C = fmaf(ln1b[layer * DD + k], w, C);
        }
        g_uq[e] = U; g_cq[e] = C;
    } else if (e < 2 * INNERD + 2 * MLPD) {
        int e2 = e - 2 * INNERD;
        int layer = e2 / MLPD, o = e2 - layer * MLPD;
        const float* W = w1 + layer * DD * MLPD + o;
        float U = 0.f, C = 0.f;
        for (int k = 0; k < DD; k++) {
            float w = W[k * MLPD];
            U = fmaf(ln2w[layer * DD + k], w, U);
            C = fmaf(ln2b[layer * DD + k], w, C);
        }
        g_u1[e2] = U; g_c1[e2] = C + b1[e2];
    }
}

// ---------------- FFMA2 register-tiled GEMM (simple, R3-best) --------------
// Input is PAIRED smem. Warp owns 4 point-pairs (8 points). Lane owns:
//   WMODE==1 (vector weights): cols NCOL*l + j  (NCOL in {2,4}), NO == 32*NCOL
//   WMODE==0 (strided):        cols l + 32*j, masked at NO
template <int NI, int NCOL, int LDIN, int WMODE, int NO, class Epi>
__device__ __forceinline__ void gemm2(const float* __restrict__ in,
                                      const float* __restrict__ W,
                                      const int ldw, Epi epi) {
    const int l  = threadIdx.x & 31;
    const int wp = threadIdx.x >> 5;
    ull acc[4][NCOL];
#pragma unroll
    for (int i = 0; i < 4; i++)
#pragma unroll
        for (int j = 0; j < NCOL; j++) acc[i][j] = 0ull;

    const float* inb = in + (wp * 4) * (2 * LDIN);
    int ni = 0;
#pragma unroll 2
    for (; ni + 4 <= NI; ni += 4) {
        ull a[4][4];
#pragma unroll
        for (int i = 0; i < 4; i++) {
            ulonglong2 t0 = *reinterpret_cast<const ulonglong2*>(inb + i * 2 * LDIN + 2 * ni);
            ulonglong2 t1 = *reinterpret_cast<const ulonglong2*>(inb + i * 2 * LDIN + 2 * ni + 4);
            a[i][0] = t0.x; a[i][1] = t0.y; a[i][2] = t1.x; a[i][3] = t1.y;
        }
#pragma unroll
        for (int k = 0; k < 4; k++) {
            ull wv[NCOL];
            if (WMODE == 1) {
                if (NCOL == 4) {
                    float4 w4 = *reinterpret_cast<const float4*>(W + (ni + k) * ldw + 4 * l);
                    wv[0] = pack2d(w4.x); wv[1] = pack2d(w4.y);
                    wv[2] = pack2d(w4.z); wv[3] = pack2d(w4.w);
                } else {
                    float2 w2 = *reinterpret_cast<const float2*>(W + (ni + k) * ldw + 2 * l);
                    wv[0] = pack2d(w2.x); wv[1] = pack2d(w2.y);
                }
            } else {
#pragma unroll
                for (int j = 0; j < NCOL; j++) {
                    int o = l + 32 * j;
                    float w = (o < NO) ? W[(ni + k) * ldw + o] : 0.f;
                    wv[j] = pack2d(w);
                }
            }
#pragma unroll
            for (int i = 0; i < 4; i++)
#pragma unroll
                for (int j = 0; j < NCOL; j++) ffma2(acc[i][j], a[i][k], wv[j]);
        }
    }
    if (NI & 2) {   // remainder of 2 (NI=90)
        ull a[4][2];
#pragma unroll
        for (int i = 0; i < 4; i++) {
            ulonglong2 t0 = *reinterpret_cast<const ulonglong2*>(inb + i * 2 * LDIN + 2 * ni);
            a[i][0] = t0.x; a[i][1] = t0.y;
        }
#pragma unroll
        for (int k = 0; k < 2; k++) {
            ull wv[NCOL];
            if (WMODE == 1) {
                if (NCOL == 4) {
                    float4 w4 = *reinterpret_cast<const float4*>(W + (ni + k) * ldw + 4 * l);
                    wv[0] = pack2d(w4.x); wv[1] = pack2d(w4.y);
                    wv[2] = pack2d(w4.z); wv[3] = pack2d(w4.w);
                } else {
                    float2 w2 = *reinterpret_cast<const float2*>(W + (ni + k) * ldw + 2 * l);
                    wv[0] = pack2d(w2.x); wv[1] = pack2d(w2.y);
                }
            } else {
#pragma unroll
                for (int j = 0; j < NCOL; j++) {
                    int o = l + 32 * j;
                    float w = (o < NO) ? W[(ni + k) * ldw + o] : 0.f;
                    wv[j] = pack2d(w);
                }
            }
#pragma unroll
            for (int i = 0; i < 4; i++)
#pragma unroll
                for (int j = 0; j < NCOL; j++) ffma2(acc[i][j], a[i][k], wv[j]);
        }
    }
#pragma unroll
    for (int i = 0; i < 4; i++)
#pragma unroll
        for (int j = 0; j < NCOL; j++) {
            int o = (WMODE == 1) ? (NCOL * l + j) : (l + 32 * j);
            if (WMODE == 1 || o < NO) epi(wp * 4 + i, o, unpack2(acc[i][j]));
        }
}

// Warp-local LN statistics only (mean, rsqrt(var)) -> st[2*pt], st[2*pt+1]
__device__ __forceinline__ void ln_stats(const float* __restrict__ src, float* __restrict__ st) {
    const int l  = threadIdx.x & 31;
    const int wp = threadIdx.x >> 5;
    const int pl = l >> 2, sub = l & 3;
    const int pt = wp * 8 + pl;
    const float* rowb = src + ((pt >> 1) * (2 * LDH) + (pt & 1));
    float s = 0.f;
    for (int f = sub; f < DD; f += 4) s += rowb[2 * f];
    s += __shfl_xor_sync(0xffffffffu, s, 1);
    s += __shfl_xor_sync(0xffffffffu, s, 2);
    float m = s * (1.0f / DD);
    float v = 0.f;
    for (int f = sub; f < DD; f += 4) { float d = rowb[2 * f] - m; v += d * d; }
    v += __shfl_xor_sync(0xffffffffu, v, 1);
    v += __shfl_xor_sync(0xffffffffu, v, 2);
    float inv = 1.0f / sqrtf(v * (1.0f / DD) + 1e-5f);
    if (sub == 0) { st[2 * pt] = m; st[2 * pt + 1] = inv; }
    __syncwarp();
}

// ---------------- fused NeRF network: 16 points / 2-warp block ----------------
// __launch_bounds__(64, 8): pin to <=128 regs (8 resident blocks) — measured
// optimum; both 7-block (130 regs) and 10-block (96 regs) configs regressed.
__global__ void __launch_bounds__(64, 8) net_kernel(NetP P, int mode /*0 coarse, 1 fine*/) {
    __shared__ __align__(16) float sh_h [(PPB / 2) * 2 * LDH ];  // 1600
    __shared__ __align__(16) float sh_s [(PPB / 2) * 2 * LDSS];  // 2112
    __shared__ __align__(16) float sh_qo[(PPB / 2) * 2 * DHD ];  // 1024 (coords/q/o aliased)
    __shared__ float sh_st[2 * PPB];   // (m, inv) per point (LN stats)
    __shared__ float sh_ip[PPB];       // 1/sum_exp per point (softmax)

    const int t  = threadIdx.x;
    const int l  = t & 31;
    const int wp = t >> 5;
    const int pl = l >> 2, sub = l & 3;
    const int base = blockIdx.x * PPB;
    const int S = mode ? NAGG : NCO;

    // ---- coords (temp in sh_qo, consumed by posenc) ----
    if (l < 24) {
        int p = l / 3, d = l - (l / 3) * 3;
        int gp = base + wp * 8 + p;
        int r = gp / S, s = gp - r * S;
        float depth = mode ? g_depths[r * NAGG + s] : coarse_depth(s);
        sh_qo[(wp * 8 + p) * 4 + d] = P.x[r * 3 + d] + P.rays[r * 3 + d] * depth;
    }
    __syncwarp();
    // ---- positional encoding ----
    for (int idx = l; idx < 8 * DD; idx += 32) {
        int p = idx / DD, f = idx - p * DD;
        int bb = (f < 45) ? f : f - 45;
        int dim = bb / 15, oct = bb - dim * 15;
        int pt = wp * 8 + p;
        float arg = sh_qo[pt * 4 + dim] * (3.14159265358979323846f * (float)(1 << oct));
        sh_h[PIDX(pt, LDH, f)] = (f < 45) ? sinf(arg) : cosf(arg);
    }
    __syncwarp();

    for (int layer = 0; layer < 2; layer++) {
        // ---- LN1 stats + attention (LN folded into wq via g_wq2/g_uq/g_cq) ----
        ln_stats(sh_h, sh_st);
        {
            float m_[8], iv_[8];
#pragma unroll
            for (int k = 0; k < 8; k++) {
                m_[k]  = sh_st[2 * (wp * 8 + k)];
                iv_[k] = sh_st[2 * (wp * 8 + k) + 1];
            }
            float2 accw[4][3];
#pragma unroll
            for (int i = 0; i < 4; i++)
#pragma unroll
                for (int j = 0; j < 3; j++) accw[i][j] = make_float2(0.f, 0.f);
            for (int head = 0; head < NHEADS; head++) {
                const float* Uq = g_uq + layer * INNERD + head * DHD;
                const float* Cq = g_cq + layer * INNERD + head * DHD;
                gemm2<DD, 2, LDH, 1, DHD>(sh_h, g_wq2 + layer * DD * INNERD + head * DHD, INNERD,
                    [&](int pr, int o, float2 v) {
                        float U = Uq[o], C = Cq[o];
                        int i2 = (pr & 3) * 2;
                        v.x = iv_[i2]     * (v.x - m_[i2]     * U) + C;
                        v.y = iv_[i2 + 1] * (v.y - m_[i2 + 1] * U) + C;
                        *reinterpret_cast<float2*>(&sh_qo[pr * 2 * DHD + 2 * o]) = v;
                    });
                __syncwarp();
                gemm2<DHD, 4, DHD, 1, PTOK>(sh_qo, g_kt + (layer * NHEADS + head) * DHD * PTOK, PTOK,
                    [&](int pr, int o, float2 v) {
                        v.x *= 0.125f; v.y *= 0.125f;
                        *reinterpret_cast<float2*>(&sh_s[pr * 2 * LDSS + 2 * o]) = v;
                    });
                __syncwarp();
                // ---- softmax over 128 keys: 4 lanes / point; stores UNNORMALIZED
                // exp, 1/sum folded into att.V epilogue ----
                {
                    const int pt = wp * 8 + pl;
                    float* rowb = sh_s + ((pt >> 1) * 2 * LDSS + (pt & 1));
                    float mx = rowb[2 * sub];
#pragma unroll
                    for (int k = 1; k < 32; k++) mx = fmaxf(mx, rowb[2 * (sub + 4 * k)]);
                    mx = fmaxf(mx, __shfl_xor_sync(0xffffffffu, mx, 1));
                    mx = fmaxf(mx, __shfl_xor_sync(0xffffffffu, mx, 2));
                    float ps = 0.f;
#pragma unroll
                    for (int k = 0; k < 32; k++) {
                        float v = __expf(rowb[2 * (sub + 4 * k)] - mx);
                        rowb[2 * (sub + 4 * k)] = v;
                        ps += v;
                    }
                    ps += __shfl_xor_sync(0xffffffffu, ps, 1);
                    ps += __shfl_xor_sync(0xffffffffu, ps, 2);
                    if (sub == 0) sh_ip[pt] = 1.0f / ps;
                }
                __syncwarp();
                gemm2<PTOK, 2, LDSS, 1, DHD>(sh_s, g_vv + (layer * NHEADS + head) * PTOK * DHD, DHD,
                    [&](int pr, int o, float2 v) {
                        v.x *= sh_ip[2 * pr];
                        v.y *= sh_ip[2 * pr + 1];
                        *reinterpret_cast<float2*>(&sh_qo[pr * 2 * DHD + 2 * o]) = v;
                    });
                __syncwarp();
                gemm2<DHD, 3, DHD, 0, DD>(sh_qo, P.wo + layer * INNERD * DD + head * DHD * DD, DD,
                    [&](int pr, int o, float2 v) {
                        int j = o >> 5, i = pr & 3;
                        accw[i][j].x += v.x; accw[i][j].y += v.y;
                    });
                __syncwarp();
            }
            const float* bo = P.bo + layer * DD;
#pragma unroll
            for (int i = 0; i < 4; i++)
#pragma unroll
                for (int j = 0; j < 3; j++) {
                    int o = l + 32 * j;
                    if (o < DD) {
                        int pr = wp * 4 + i;
                        float2* addr = reinterpret_cast<float2*>(&sh_h[pr * 2 * LDH + 2 * o]);
                        float2 h = *addr;
                        float bb = bo[o];
                        h.x += accw[i][j].x + bb;
                        h.y += accw[i][j].y + bb;
                        *addr = h;
                    }
                }
            __syncwarp();
        }
        // ---- LN2 stats + MLP (LN folded into w1 via g_w12/g_u1/g_c1) ----
        ln_stats(sh_h, sh_st);
        {
            float m_[8], iv_[8];
#pragma unroll
            for (int k = 0; k < 8; k++) {
                m_[k]  = sh_st[2 * (wp * 8 + k)];
                iv_[k] = sh_st[2 * (wp * 8 + k) + 1];
            }
            float2 accm[4][3];
#pragma unroll
            for (int i = 0; i < 4; i++)
#pragma unroll
                for (int j = 0; j < 3; j++) accm[i][j] = make_float2(0.f, 0.f);
            for (int c = 0; c < MLPD / 128; c++) {
                const float* U1 = g_u1 + layer * MLPD + c * 128;
                const float* C1 = g_c1 + layer * MLPD + c * 128;
                gemm2<DD, 4, LDH, 1, 128>(sh_h, g_w12 + layer * DD * MLPD + c * 128, MLPD,
                    [&](int pr, int o, float2 v) {
                        float U = U1[o], C = C1[o];
                        int i2 = (pr & 3) * 2;
                        float x0 = iv_[i2]     * (v.x - m_[i2]     * U) + C;
                        float x1 = iv_[i2 + 1] * (v.y - m_[i2 + 1] * U) + C;
                        v.x = 0.5f * x0 * (1.0f + erff(x0 * 0.70710678118654752f));
                        v.y = 0.5f * x1 * (1.0f + erff(x1 * 0.70710678118654752f));
                        *reinterpret_cast<float2*>(&sh_s[pr * 2 * LDSS + 2 * o]) = v;
                    });
                __syncwarp();
                gemm2<128, 3, LDSS, 0, DD>(sh_s, P.w2 + layer * MLPD * DD + c * 128 * DD, DD,
                    [&](int pr, int o, float2 v) {
                        int j = o >> 5, i = pr & 3;
                        accm[i][j].x += v.x; accm[i][j].y += v.y;
                    });
                __syncwarp();
            }
            const float* b2 = P.b2 + layer * DD;
#pragma unroll
            for (int i = 0; i < 4; i++)
#pragma unroll
                for (int j = 0; j < 3; j++) {
                    int o = l + 32 * j;
                    if (o < DD) {
                        int pr = wp * 4 + i;
                        float2* addr = reinterpret_cast<float2*>(&sh_h[pr * 2 * LDH + 2 * o]);
                        float2 h = *addr;
                        float bb = b2[o];
                        h.x += accm[i][j].x + bb;
                        h.y += accm[i][j].y + bb;
                        *addr = h;
                    }
                }
            __syncwarp();
        }
    }

    // ---- density head ----
    gemm2<DD, 4, LDH, 1, 128>(sh_h, P.wd1, 128,
        [&](int pr, int o, float2 v) {
            float bb = P.bd1[o];
            v.x = fmaxf(v.x + bb, 0.f); v.y = fmaxf(v.y + bb, 0.f);
            *reinterpret_cast<float2*>(&sh_s[pr * 2 * LDSS + 2 * o]) = v;
        });
    __syncwarp();
    {
        const int pt = wp * 8 + pl;
        const float* rowb = sh_s + ((pt >> 1) * 2 * LDSS + (pt & 1));
        float a = 0.f;
#pragma unroll
        for (int k = 0; k < 32; k++) a = fmaf(rowb[2 * (sub + 4 * k)], P.wd2[sub + 4 * k], a);
        a += __shfl_xor_sync(0xffffffffu, a, 1);
        a += __shfl_xor_sync(0xffffffffu, a, 2);
        if (sub == 0) {
            a += P.bd2[0];
            float sp = fmaxf(a, 0.f) + log1pf(__expf(-fabsf(a)));
            float* dst = mode ? g_dens_f : g_dens_c;
            dst[base + pt] = sp;
        }
    }
    __syncwarp();
    // ---- color head ----
    gemm2<DD, 4, LDH, 1, 128>(sh_h, P.wc1, 128,
        [&](int pr, int o, float2 v) {
            float bb = P.bc1[o];
            v.x = fmaxf(v.x + bb, 0.f); v.y = fmaxf(v.y + bb, 0.f);
            *reinterpret_cast<float2*>(&sh_s[pr * 2 * LDSS + 2 * o]) = v;
        });
    __syncwarp();
    {
        const int pt = wp * 8 + pl;
        const float* rowb = sh_s + ((pt >> 1) * 2 * LDSS + (pt & 1));
        float c0 = 0.f, c1 = 0.f, c2 = 0.f;
#pragma unroll
        for (int k = 0; k < 32; k++) {
            float v = rowb[2 * (sub + 4 * k)];
            const float* wr = P.wc2 + (sub + 4 * k) * 3;
            c0 = fmaf(v, wr[0], c0);
            c1 = fmaf(v, wr[1], c1);
            c2 = fmaf(v, wr[2], c2);
        }
        c0 += __shfl_xor_sync(0xffffffffu, c0, 1);
        c0 += __shfl_xor_sync(0xffffffffu, c0, 2);
        c1 += __shfl_xor_sync(0xffffffffu, c1, 1);
        c1 += __shfl_xor_sync(0xffffffffu, c1, 2);
        c2 += __shfl_xor_sync(0xffffffffu, c2, 1);
        c2 += __shfl_xor_sync(0xffffffffu, c2, 2);
        if (sub == 0) {
            int gp = base + pt;
            float* dst = mode ? g_col_f : g_col_c;
            dst[gp * 3 + 0] = 1.0f / (1.0f + __expf(-(c0 + P.bc2[0])));
            dst[gp * 3 + 1] = 1.0f / (1.0f + __expf(-(c1 + P.bc2[1])));
            dst[gp * 3 + 2] = 1.0f / (1.0f + __expf(-(c2 + P.bc2[2])));
        }
    }
}

// ---------------- coarse render + PDF resampling + merge ----------------
__global__ void coarse_post_kernel(float* __restrict__ out) {
    int r = blockIdx.x * blockDim.x + threadIdx.x;
    if (r >= RAYS) return;
    float cd[NCO];
    for (int s = 0; s < NCO; s++) cd[s] = coarse_depth(s);

    float w[NCO];
    float T = 1.f, acc = 0.f, rgb0 = 0.f, rgb1 = 0.f, rgb2 = 0.f, dsum = 0.f;
    for (int s = 0; s < NCO; s++) {
        float seg = (s < NCO - 1) ? cd[s + 1] - cd[s] : 1e10f;
        float dens = g_dens_c[r * NCO + s];
        float alpha = 1.0f - expf(-dens * seg);
        float wi = alpha * T;
        w[s] = wi;
        T *= (1.0f - alpha + 1e-10f);
        acc += wi;
        rgb0 += wi * g_col_c[(r * NCO + s) * 3 + 0];
        rgb1 += wi * g_col_c[(r * NCO + s) * 3 + 1];
        rgb2 += wi * g_col_c[(r * NCO + s) * 3 + 2];
        dsum += wi * cd[s];
    }
    float inv = 1.0f / (acc + 1e-8f);
    out[3072 + r * 3 + 0] = 1.0f - acc + (rgb0 * inv) * acc;
    out[3072 + r * 3 + 1] = 1.0f - acc + (rgb1 * inv) * acc;
    out[3072 + r * 3 + 2] = 1.0f - acc + (rgb2 * inv) * acc;
    out[7168 + r] = dsum * inv;

    float bins[63], cdf[63];
    for (int i = 0; i < 63; i++) bins[i] = 0.5f * (cd[i] + cd[i + 1]);
    float wsum = 0.f;
    for (int i = 0; i < 62; i++) wsum += w[i + 1] + 1e-5f;
    cdf[0] = 0.f;
    float c0 = 0.f;
    for (int i = 0; i < 62; i++) { c0 += (w[i + 1] + 1e-5f) / wsum; cdf[i + 1] = c0; }

    float fd[NFI];
    for (int j = 0; j < NFI; j++) {
        float u = (j + 0.5f) * (1.0f / NFI);
        int ind = 0;
        for (int k = 0; k < 63; k++) if (cdf[k] <= u) ind = k + 1;
        int below = ind - 1; if (below < 0) below = 0; if (below > 62) below = 62;
        int above = ind;     if (above > 62) above = 62;
        float cb = cdf[below], ca = cdf[above];
        float bb = bins[below], ba = bins[above];
        float denom = ca - cb;
        if (denom < 1e-5f) denom = 1.0f;
        fd[j] = bb + (u - cb) / denom * (ba - bb);
    }
    int i = 0, j = 0;
    for (int k = 0; k < NAGG; k++) {
        float v;
        if (j >= NFI || (i < NCO && cd[i] <= fd[j])) v = cd[i++];
        else v = fd[j++];
        g_depths[r * NAGG + k] = v;
    }
}

// ---------------- fine render ----------------
__global__ void fine_post_kernel(float* __restrict__ out) {
    int r = blockIdx.x * blockDim.x + threadIdx.x;
    if (r >= RAYS) return;
    float d[NAGG];
    for (int s = 0; s < NAGG; s++) d[s] = g_depths[r * NAGG + s];
    float T = 1.f, acc = 0.f, rgb0 = 0.f, rgb1 = 0.f, rgb2 = 0.f, dsum = 0.f;
    for (int s = 0; s < NAGG; s++) {
        float seg = (s < NAGG - 1) ? d[s + 1] - d[s] : 1e10f;
        float dens = g_dens_f[r * NAGG + s];
        float alpha = 1.0f - expf(-dens * seg);
        float wi = alpha * T;
        T *= (1.0f - alpha + 1e-10f);
        acc += wi;
        rgb0 += wi * g_col_f[(r * NAGG + s) * 3 + 0];
        rgb1 += wi * g_col_f[(r * NAGG + s) * 3 + 1];
        rgb2 += wi * g_col_f[(r * NAGG + s) * 3 + 2];
        dsum += wi * d[s];
    }
    float inv = 1.0f / (acc + 1e-8f);
    out[r * 3 + 0] = 1.0f - acc + (rgb0 * inv) * acc;
    out[r * 3 + 1] = 1.0f - acc + (rgb1 * inv) * acc;
    out[r * 3 + 2] = 1.0f - acc + (rgb2 * inv) * acc;
    out[6144 + r] = dsum * inv;
}

// ---------------- launch ----------------
extern "C" void kernel_launch(void* const* d_in, const int* in_sizes, int n_in,
                              void* d_out, int out_size) {
    const float* z    = (const float*)d_in[0];
    NetP P;
    P.x    = (const float*)d_in[1];
    P.rays = (const float*)d_in[2];
    const float* ln1w = (const float*)d_in[3];
    const float* ln1b = (const float*)d_in[4];
    const float* wq   = (const float*)d_in[5];
    const float* wkv  = (const float*)d_in[6];
    P.wo   = (const float*)d_in[7];
    P.bo   = (const float*)d_in[8];
    const float* ln2w = (const float*)d_in[9];
    const float* ln2b = (const float*)d_in[10];
    const float* w1   = (const float*)d_in[11];
    const float* b1   = (const float*)d_in[12];
    P.w2   = (const float*)d_in[13];
    P.b2   = (const float*)d_in[14];
    P.wc1  = (const float*)d_in[15];
    P.bc1  = (const float*)d_in[16];
    P.wc2  = (const float*)d_in[17];
    P.bc2  = (const float*)d_in[18];
    P.wd1  = (const float*)d_in[19];
    P.bd1  = (const float*)d_in[20];
    P.wd2  = (const float*)d_in[21];
    P.bd2  = (const float*)d_in[22];
    float* out = (float*)d_out;

    const int FOLD_N = 2 * DD * INNERD + 2 * DD * MLPD;
    kv_kernel<<<(2 * PTOK * 2 * INNERD + 255) / 256, 256>>>(z, wkv);
    fold_scale_kernel<<<(FOLD_N + 255) / 256, 256>>>(ln1w, wq, ln2w, w1);
    fold_uc_kernel<<<(2 * INNERD + 2 * MLPD + 255) / 256, 256>>>(ln1w, ln1b, wq, ln2w, ln2b, w1, b1);
    net_kernel<<<(RAYS * NCO) / PPB, 64>>>(P, 0);
    coarse_post_kernel<<<(RAYS + 127) / 128, 128>>>(out);
    net_kernel<<<(RAYS * NAGG) / PPB, 64>>>(P, 1);
    fine_post_kernel<<<(RAYS + 127) / 128, 128>>>(out);
}

// round 16
// speedup vs baseline: 1.7348x; 1.6107x over previous
#include <cuda_runtime.h>
#include <math.h>

typedef unsigned long long ull;

// ---------------- problem constants ----------------
#define RAYS    1024
#define NCO     64
#define NFI     32
#define NAGG    96
#define MIND    0.035f
#define MAXD    35.0f
#define DD      90
#define NHEADS  12
#define DHD     64
#define INNERD  768
#define MLPD    1536
#define KVD     768
#define PTOK    128
#define LDH     100     // paired row stride 2*LDH=200 (== 8 mod 32 -> conflict-free)
#define LDSS    132     // paired row stride 2*LDSS=264 (== 8 mod 32)
#define PPB     16      // points per block (2 warps x 8 points = 4 pairs/warp)

// ---------------- device scratch ----------------
__device__ float g_kt   [2*NHEADS*DHD*PTOK];   // [layer][head][d][key]
__device__ float g_vv   [2*NHEADS*PTOK*DHD];   // [layer][head][key][d]
__device__ float g_dens_c[RAYS*NCO];
__device__ float g_col_c [RAYS*NCO*3];
__device__ float g_dens_f[RAYS*NFI];           // FINE-ONLY points (32/ray)
__device__ float g_col_f [RAYS*NFI*3];
__device__ float g_depths [RAYS*NAGG];         // merged depths (for rendering)
__device__ float g_fdepths[RAYS*NFI];          // fine sample depths (net input)
__device__ int   g_src    [RAYS*NAGG];         // merge provenance: <NCO coarse idx, else NCO+fine idx
// LN-folded weights: W' = diag(ln_w) @ W ; U = colsum(diag(ln_w)@W) ; C = ln_b @ W (+bias)
__device__ float g_wq2[2*DD*INNERD];
__device__ float g_uq [2*INNERD];
__device__ float g_cq [2*INNERD];
__device__ float g_w12[2*DD*MLPD];
__device__ float g_u1 [2*MLPD];
__device__ float g_c1 [2*MLPD];   // includes b1

struct NetP {
    const float *x, *rays;
    const float *wo, *bo, *w2, *b2;
    const float *wc1, *bc1, *wc2, *bc2, *wd1, *bd1, *wd2, *bd2;
};

__device__ __forceinline__ float coarse_depth(int s) {
    const float step = (MAXD - MIND) / 64.0f;
    return 0.5f * ((MIND + s * step) + (MIND + (s + 1) * step));
}

// ---------------- f32x2 helpers ----------------
__device__ __forceinline__ ull pack2(float x, float y) {
    ull r; asm("mov.b64 %0, {%1, %2};" : "=l"(r) : "f"(x), "f"(y)); return r;
}
__device__ __forceinline__ ull pack2d(float x) { return pack2(x, x); }
__device__ __forceinline__ void ffma2(ull& d, ull a, ull b) {
    asm("fma.rn.f32x2 %0, %1, %2, %0;" : "+l"(d) : "l"(a), "l"(b));
}
__device__ __forceinline__ float2 unpack2(ull v) {
    float2 r; asm("mov.b64 {%0, %1}, %2;" : "=f"(r.x), "=f"(r.y) : "l"(v)); return r;
}

// paired activation layout: buf[(p>>1)*2*LD + 2*k + (p&1)]
#define PIDX(p, LD, k) (((p) >> 1) * (2 * (LD)) + 2 * (k) + ((p) & 1))

// ---------------- KV precompute ----------------
__global__ void kv_kernel(const float* __restrict__ z, const float* __restrict__ wkv) {
    int e = blockIdx.x * blockDim.x + threadIdx.x;
    if (e >= 2 * PTOK * 2 * INNERD) return;
    int layer = e / (PTOK * 2 * INNERD);
    int rem   = e - layer * (PTOK * 2 * INNERD);
    int p   = rem / (2 * INNERD);
    int col = rem - p * (2 * INNERD);
    const float* zr = z + p * KVD;
    const float* wc = wkv + layer * KVD * 2 * INNERD + col;
    float acc = 0.f;
#pragma unroll 8
    for (int k = 0; k < KVD; k++) acc = fmaf(zr[k], wc[k * 2 * INNERD], acc);
    int head = col >> 7, c = col & 127;
    if (c < DHD) g_kt[((layer * NHEADS + head) * DHD + c) * PTOK + p] = acc;
    else         g_vv[((layer * NHEADS + head) * PTOK + p) * DHD + (c - DHD)] = acc;
}

// ---------------- LN-fold precompute ----------------
__global__ void fold_scale_kernel(const float* __restrict__ ln1w, const float* __restrict__ wq,
                                  const float* __restrict__ ln2w, const float* __restrict__ w1) {
    int e = blockIdx.x * blockDim.x + threadIdx.x;
    const int T1 = 2 * DD * INNERD;
    if (e < T1) {
        int layer = e / (DD * INNERD);
        int k = (e - layer * DD * INNERD) / INNERD;
        g_wq2[e] = ln1w[layer * DD + k] * wq[e];
    } else if (e < T1 + 2 * DD * MLPD) {
        int e2 = e - T1;
        int layer = e2 / (DD * MLPD);
        int k = (e2 - layer * DD * MLPD) / MLPD;
        g_w12[e2] = ln2w[layer * DD + k] * w1[e2];
    }
}

__global__ void fold_uc_kernel(const float* __restrict__ ln1w, const float* __restrict__ ln1b,
                               const float* __restrict__ wq,
                               const float* __restrict__ ln2w, const float* __restrict__ ln2b,
                               const float* __restrict__ w1, const float* __restrict__ b1) {
    int e = blockIdx.x * blockDim.x + threadIdx.x;
    if (e < 2 * INNERD) {
        int layer = e / INNERD, o = e - layer * INNERD;
        const float* W = wq + layer * DD * INNERD + o;
        float U = 0.f, C = 0.f;
        for (int k = 0; k < DD; k++) {
            float w = W[k * INNERD];
            U = fmaf(ln1w[layer * DD + k], w, U);
            C = fmaf(ln1b[layer * DD + k], w, C);
        }
        g_uq[e] = U; g_cq[e] = C;
    } else if (e < 2 * INNERD + 2 * MLPD) {
        int e2 = e - 2 * INNERD;
        int layer = e2 / MLPD, o = e2 - layer * MLPD;
        const float* W = w1 + layer * DD * MLPD + o;
        float U = 0.f, C = 0.f;
        for (int k = 0; k < DD; k++) {
            float w = W[k * MLPD];
            U = fmaf(ln2w[layer * DD + k], w, U);
            C = fmaf(ln2b[layer * DD + k], w, C);
        }
        g_u1[e2] = U; g_c1[e2] = C + b1[e2];
    }
}

// ---------------- FFMA2 register-tiled GEMM (simple, R3-best) --------------
// Input is PAIRED smem. Warp owns 4 point-pairs (8 points). Lane owns:
//   WMODE==1 (vector weights): cols NCOL*l + j  (NCOL in {2,4}), NO == 32*NCOL
//   WMODE==0 (strided):        cols l + 32*j, masked at NO
template <int NI, int NCOL, int LDIN, int WMODE, int NO, class Epi>
__device__ __forceinline__ void gemm2(const float* __restrict__ in,
                                      const float* __restrict__ W,
                                      const int ldw, Epi epi) {
    const int l  = threadIdx.x & 31;
    const int wp = threadIdx.x >> 5;
    ull acc[4][NCOL];
#pragma unroll
    for (int i = 0; i < 4; i++)
#pragma unroll
        for (int j = 0; j < NCOL; j++) acc[i][j] = 0ull;

    const float* inb = in + (wp * 4) * (2 * LDIN);
    int ni = 0;
#pragma unroll 2
    for (; ni + 4 <= NI; ni += 4) {
        ull a[4][4];
#pragma unroll
        for (int i = 0; i < 4; i++) {
            ulonglong2 t0 = *reinterpret_cast<const ulonglong2*>(inb + i * 2 * LDIN + 2 * ni);
            ulonglong2 t1 = *reinterpret_cast<const ulonglong2*>(inb + i * 2 * LDIN + 2 * ni + 4);
            a[i][0] = t0.x; a[i][1] = t0.y; a[i][2] = t1.x; a[i][3] = t1.y;
        }
#pragma unroll
        for (int k = 0; k < 4; k++) {
            ull wv[NCOL];
            if (WMODE == 1) {
                if (NCOL == 4) {
                    float4 w4 = *reinterpret_cast<const float4*>(W + (ni + k) * ldw + 4 * l);
                    wv[0] = pack2d(w4.x); wv[1] = pack2d(w4.y);
                    wv[2] = pack2d(w4.z); wv[3] = pack2d(w4.w);
                } else {
                    float2 w2 = *reinterpret_cast<const float2*>(W + (ni + k) * ldw + 2 * l);
                    wv[0] = pack2d(w2.x); wv[1] = pack2d(w2.y);
                }
            } else {
#pragma unroll
                for (int j = 0; j < NCOL; j++) {
                    int o = l + 32 * j;
                    float w = (o < NO) ? W[(ni + k) * ldw + o] : 0.f;
                    wv[j] = pack2d(w);
                }
            }
#pragma unroll
            for (int i = 0; i < 4; i++)
#pragma unroll
                for (int j = 0; j < NCOL; j++) ffma2(acc[i][j], a[i][k], wv[j]);
        }
    }
    if (NI & 2) {   // remainder of 2 (NI=90)
        ull a[4][2];
#pragma unroll
        for (int i = 0; i < 4; i++) {
            ulonglong2 t0 = *reinterpret_cast<const ulonglong2*>(inb + i * 2 * LDIN + 2 * ni);
            a[i][0] = t0.x; a[i][1] = t0.y;
        }
#pragma unroll
        for (int k = 0; k < 2; k++) {
            ull wv[NCOL];
            if (WMODE == 1) {
                if (NCOL == 4) {
                    float4 w4 = *reinterpret_cast<const float4*>(W + (ni + k) * ldw + 4 * l);
                    wv[0] = pack2d(w4.x); wv[1] = pack2d(w4.y);
                    wv[2] = pack2d(w4.z); wv[3] = pack2d(w4.w);
                } else {
                    float2 w2 = *reinterpret_cast<const float2*>(W + (ni + k) * ldw + 2 * l);
                    wv[0] = pack2d(w2.x); wv[1] = pack2d(w2.y);
                }
            } else {
#pragma unroll
                for (int j = 0; j < NCOL; j++) {
                    int o = l + 32 * j;
                    float w = (o < NO) ? W[(ni + k) * ldw + o] : 0.f;
                    wv[j] = pack2d(w);
                }
            }
#pragma unroll
            for (int i = 0; i < 4; i++)
#pragma unroll
                for (int j = 0; j < NCOL; j++) ffma2(acc[i][j], a[i][k], wv[j]);
        }
    }
#pragma unroll
    for (int i = 0; i < 4; i++)
#pragma unroll
        for (int j = 0; j < NCOL; j++) {
            int o = (WMODE == 1) ? (NCOL * l + j) : (l + 32 * j);
            if (WMODE == 1 || o < NO) epi(wp * 4 + i, o, unpack2(acc[i][j]));
        }
}

// Warp-local LN statistics only (mean, rsqrt(var)) -> st[2*pt], st[2*pt+1]
__device__ __forceinline__ void ln_stats(const float* __restrict__ src, float* __restrict__ st) {
    const int l  = threadIdx.x & 31;
    const int wp = threadIdx.x >> 5;
    const int pl = l >> 2, sub = l & 3;
    const int pt = wp * 8 + pl;
    const float* rowb = src + ((pt >> 1) * (2 * LDH) + (pt & 1));
    float s = 0.f;
    for (int f = sub; f < DD; f += 4) s += rowb[2 * f];
    s += __shfl_xor_sync(0xffffffffu, s, 1);
    s += __shfl_xor_sync(0xffffffffu, s, 2);
    float m = s * (1.0f / DD);
    float v = 0.f;
    for (int f = sub; f < DD; f += 4) { float d = rowb[2 * f] - m; v += d * d; }
    v += __shfl_xor_sync(0xffffffffu, v, 1);
    v += __shfl_xor_sync(0xffffffffu, v, 2);
    float inv = 1.0f / sqrtf(v * (1.0f / DD) + 1e-5f);
    if (sub == 0) { st[2 * pt] = m; st[2 * pt + 1] = inv; }
    __syncwarp();
}

// ---------------- fused NeRF network: 16 points / 2-warp block ----------------
// mode 0: coarse (64 samples/ray, analytic depths). mode 1: fine (32 NEW
// samples/ray, depths from g_fdepths). Coarse points of the merged fine set
// are NOT recomputed — the network is pointwise, so their outputs are gathered
// from the coarse pass in fine_post_kernel via g_src.
// __launch_bounds__(64, 8): pin to <=128 regs (8 resident blocks) — measured optimum.
__global__ void __launch_bounds__(64, 8) net_kernel(NetP P, int mode) {
    __shared__ __align__(16) float sh_h [(PPB / 2) * 2 * LDH ];  // 1600
    __shared__ __align__(16) float sh_s [(PPB / 2) * 2 * LDSS];  // 2112
    __shared__ __align__(16) float sh_qo[(PPB / 2) * 2 * DHD ];  // 1024 (coords/q/o aliased)
    __shared__ float sh_st[2 * PPB];   // (m, inv) per point (LN stats)
    __shared__ float sh_ip[PPB];       // 1/sum_exp per point (softmax)

    const int t  = threadIdx.x;
    const int l  = t & 31;
    const int wp = t >> 5;
    const int pl = l >> 2, sub = l & 3;
    const int base = blockIdx.x * PPB;
    const int S = mode ? NFI : NCO;

    // ---- coords (temp in sh_qo, consumed by posenc) ----
    if (l < 24) {
        int p = l / 3, d = l - (l / 3) * 3;
        int gp = base + wp * 8 + p;
        int r = gp / S, s = gp - r * S;
        float depth = mode ? g_fdepths[r * NFI + s] : coarse_depth(s);
        sh_qo[(wp * 8 + p) * 4 + d] = P.x[r * 3 + d] + P.rays[r * 3 + d] * depth;
    }
    __syncwarp();
    // ---- positional encoding ----
    for (int idx = l; idx < 8 * DD; idx += 32) {
        int p = idx / DD, f = idx - p * DD;
        int bb = (f < 45) ? f : f - 45;
        int dim = bb / 15, oct = bb - dim * 15;
        int pt = wp * 8 + p;
        float arg = sh_qo[pt * 4 + dim] * (3.14159265358979323846f * (float)(1 << oct));
        sh_h[PIDX(pt, LDH, f)] = (f < 45) ? sinf(arg) : cosf(arg);
    }
    __syncwarp();

    for (int layer = 0; layer < 2; layer++) {
        // ---- LN1 stats + attention (LN folded into wq via g_wq2/g_uq/g_cq) ----
        ln_stats(sh_h, sh_st);
        {
            float m_[8], iv_[8];
#pragma unroll
            for (int k = 0; k < 8; k++) {
                m_[k]  = sh_st[2 * (wp * 8 + k)];
                iv_[k] = sh_st[2 * (wp * 8 + k) + 1];
            }
            float2 accw[4][3];
#pragma unroll
            for (int i = 0; i < 4; i++)
#pragma unroll
                for (int j = 0; j < 3; j++) accw[i][j] = make_float2(0.f, 0.f);
            for (int head = 0; head < NHEADS; head++) {
                const float* Uq = g_uq + layer * INNERD + head * DHD;
                const float* Cq = g_cq + layer * INNERD + head * DHD;
                gemm2<DD, 2, LDH, 1, DHD>(sh_h, g_wq2 + layer * DD * INNERD + head * DHD, INNERD,
                    [&](int pr, int o, float2 v) {
                        float U = Uq[o], C = Cq[o];
                        int i2 = (pr & 3) * 2;
                        v.x = iv_[i2]     * (v.x - m_[i2]     * U) + C;
                        v.y = iv_[i2 + 1] * (v.y - m_[i2 + 1] * U) + C;
                        *reinterpret_cast<float2*>(&sh_qo[pr * 2 * DHD + 2 * o]) = v;
                    });
                __syncwarp();
                gemm2<DHD, 4, DHD, 1, PTOK>(sh_qo, g_kt + (layer * NHEADS + head) * DHD * PTOK, PTOK,
                    [&](int pr, int o, float2 v) {
                        v.x *= 0.125f; v.y *= 0.125f;
                        *reinterpret_cast<float2*>(&sh_s[pr * 2 * LDSS + 2 * o]) = v;
                    });
                __syncwarp();
                // ---- softmax over 128 keys: 4 lanes / point; stores UNNORMALIZED
                // exp, 1/sum folded into att.V epilogue ----
                {
                    const int pt = wp * 8 + pl;
                    float* rowb = sh_s + ((pt >> 1) * 2 * LDSS + (pt & 1));
                    float mx = rowb[2 * sub];
#pragma unroll
                    for (int k = 1; k < 32; k++) mx = fmaxf(mx, rowb[2 * (sub + 4 * k)]);
                    mx = fmaxf(mx, __shfl_xor_sync(0xffffffffu, mx, 1));
                    mx = fmaxf(mx, __shfl_xor_sync(0xffffffffu, mx, 2));
                    float ps = 0.f;
#pragma unroll
                    for (int k = 0; k < 32; k++) {
                        float v = __expf(rowb[2 * (sub + 4 * k)] - mx);
                        rowb[2 * (sub + 4 * k)] = v;
                        ps += v;
                    }
                    ps += __shfl_xor_sync(0xffffffffu, ps, 1);
                    ps += __shfl_xor_sync(0xffffffffu, ps, 2);
                    if (sub == 0) sh_ip[pt] = 1.0f / ps;
                }
                __syncwarp();
                gemm2<PTOK, 2, LDSS, 1, DHD>(sh_s, g_vv + (layer * NHEADS + head) * PTOK * DHD, DHD,
                    [&](int pr, int o, float2 v) {
                        v.x *= sh_ip[2 * pr];
                        v.y *= sh_ip[2 * pr + 1];
                        *reinterpret_cast<float2*>(&sh_qo[pr * 2 * DHD + 2 * o]) = v;
                    });
                __syncwarp();
                gemm2<DHD, 3, DHD, 0, DD>(sh_qo, P.wo + layer * INNERD * DD + head * DHD * DD, DD,
                    [&](int pr, int o, float2 v) {
                        int j = o >> 5, i = pr & 3;
                        accw[i][j].x += v.x; accw[i][j].y += v.y;
                    });
                __syncwarp();
            }
            const float* bo = P.bo + layer * DD;
#pragma unroll
            for (int i = 0; i < 4; i++)
#pragma unroll
                for (int j = 0; j < 3; j++) {
                    int o = l + 32 * j;
                    if (o < DD) {
                        int pr = wp * 4 + i;
                        float2* addr = reinterpret_cast<float2*>(&sh_h[pr * 2 * LDH + 2 * o]);
                        float2 h = *addr;
                        float bb = bo[o];
                        h.x += accw[i][j].x + bb;
                        h.y += accw[i][j].y + bb;
                        *addr = h;
                    }
                }
            __syncwarp();
        }
        // ---- LN2 stats + MLP (LN folded into w1 via g_w12/g_u1/g_c1) ----
        ln_stats(sh_h, sh_st);
        {
            float m_[8], iv_[8];
#pragma unroll
            for (int k = 0; k < 8; k++) {
                m_[k]  = sh_st[2 * (wp * 8 + k)];
                iv_[k] = sh_st[2 * (wp * 8 + k) + 1];
            }
            float2 accm[4][3];
#pragma unroll
            for (int i = 0; i < 4; i++)
#pragma unroll
                for (int j = 0; j < 3; j++) accm[i][j] = make_float2(0.f, 0.f);
            for (int c = 0; c < MLPD / 128; c++) {
                const float* U1 = g_u1 + layer * MLPD + c * 128;
                const float* C1 = g_c1 + layer * MLPD + c * 128;
                gemm2<DD, 4, LDH, 1, 128>(sh_h, g_w12 + layer * DD * MLPD + c * 128, MLPD,
                    [&](int pr, int o, float2 v) {
                        float U = U1[o], C = C1[o];
                        int i2 = (pr & 3) * 2;
                        float x0 = iv_[i2]     * (v.x - m_[i2]     * U) + C;
                        float x1 = iv_[i2 + 1] * (v.y - m_[i2 + 1] * U) + C;
                        v.x = 0.5f * x0 * (1.0f + erff(x0 * 0.70710678118654752f));
                        v.y = 0.5f * x1 * (1.0f + erff(x1 * 0.70710678118654752f));
                        *reinterpret_cast<float2*>(&sh_s[pr * 2 * LDSS + 2 * o]) = v;
                    });
                __syncwarp();
                gemm2<128, 3, LDSS, 0, DD>(sh_s, P.w2 + layer * MLPD * DD + c * 128 * DD, DD,
                    [&](int pr, int o, float2 v) {
                        int j = o >> 5, i = pr & 3;
                        accm[i][j].x += v.x; accm[i][j].y += v.y;
                    });
                __syncwarp();
            }
            const float* b2 = P.b2 + layer * DD;
#pragma unroll
            for (int i = 0; i < 4; i++)
#pragma unroll
                for (int j = 0; j < 3; j++) {
                    int o = l + 32 * j;
                    if (o < DD) {
                        int pr = wp * 4 + i;
                        float2* addr = reinterpret_cast<float2*>(&sh_h[pr * 2 * LDH + 2 * o]);
                        float2 h = *addr;
                        float bb = b2[o];
                        h.x += accm[i][j].x + bb;
                        h.y += accm[i][j].y + bb;
                        *addr = h;
                    }
                }
            __syncwarp();
        }
    }

    // ---- density head ----
    gemm2<DD, 4, LDH, 1, 128>(sh_h, P.wd1, 128,
        [&](int pr, int o, float2 v) {
            float bb = P.bd1[o];
            v.x = fmaxf(v.x + bb, 0.f); v.y = fmaxf(v.y + bb, 0.f);
            *reinterpret_cast<float2*>(&sh_s[pr * 2 * LDSS + 2 * o]) = v;
        });
    __syncwarp();
    {
        const int pt = wp * 8 + pl;
        const float* rowb = sh_s + ((pt >> 1) * 2 * LDSS + (pt & 1));
        float a = 0.f;
#pragma unroll
        for (int k = 0; k < 32; k++) a = fmaf(rowb[2 * (sub + 4 * k)], P.wd2[sub + 4 * k], a);
        a += __shfl_xor_sync(0xffffffffu, a, 1);
        a += __shfl_xor_sync(0xffffffffu, a, 2);
        if (sub == 0) {
            a += P.bd2[0];
            float sp = fmaxf(a, 0.f) + log1pf(__expf(-fabsf(a)));
            float* dst = mode ? g_dens_f : g_dens_c;
            dst[base + pt] = sp;
        }
    }
    __syncwarp();
    // ---- color head ----
    gemm2<DD, 4, LDH, 1, 128>(sh_h, P.wc1, 128,
        [&](int pr, int o, float2 v) {
            float bb = P.bc1[o];
            v.x = fmaxf(v.x + bb, 0.f); v.y = fmaxf(v.y + bb, 0.f);
            *reinterpret_cast<float2*>(&sh_s[pr * 2 * LDSS + 2 * o]) = v;
        });
    __syncwarp();
    {
        const int pt = wp * 8 + pl;
        const float* rowb = sh_s + ((pt >> 1) * 2 * LDSS + (pt & 1));
        float c0 = 0.f, c1 = 0.f, c2 = 0.f;
#pragma unroll
        for (int k = 0; k < 32; k++) {
            float v = rowb[2 * (sub + 4 * k)];
            const float* wr = P.wc2 + (sub + 4 * k) * 3;
            c0 = fmaf(v, wr[0], c0);
            c1 = fmaf(v, wr[1], c1);
            c2 = fmaf(v, wr[2], c2);
        }
        c0 += __shfl_xor_sync(0xffffffffu, c0, 1);
        c0 += __shfl_xor_sync(0xffffffffu, c0, 2);
        c1 += __shfl_xor_sync(0xffffffffu, c1, 1);
        c1 += __shfl_xor_sync(0xffffffffu, c1, 2);
        c2 += __shfl_xor_sync(0xffffffffu, c2, 1);
        c2 += __shfl_xor_sync(0xffffffffu, c2, 2);
        if (sub == 0) {
            int gp = base + pt;
            float* dst = mode ? g_col_f : g_col_c;
            dst[gp * 3 + 0] = 1.0f / (1.0f + __expf(-(c0 + P.bc2[0])));
            dst[gp * 3 + 1] = 1.0f / (1.0f + __expf(-(c1 + P.bc2[1])));
            dst[gp * 3 + 2] = 1.0f / (1.0f + __expf(-(c2 + P.bc2[2])));
        }
    }
}

// ---------------- coarse render + PDF resampling + merge (with provenance) ---
__global__ void coarse_post_kernel(float* __restrict__ out) {
    int r = blockIdx.x * blockDim.x + threadIdx.x;
    if (r >= RAYS) return;
    float cd[NCO];
    for (int s = 0; s < NCO; s++) cd[s] = coarse_depth(s);

    float w[NCO];
    float T = 1.f, acc = 0.f, rgb0 = 0.f, rgb1 = 0.f, rgb2 = 0.f, dsum = 0.f;
    for (int s = 0; s < NCO; s++) {
        float seg = (s < NCO - 1) ? cd[s + 1] - cd[s] : 1e10f;
        float dens = g_dens_c[r * NCO + s];
        float alpha = 1.0f - expf(-dens * seg);
        float wi = alpha * T;
        w[s] = wi;
        T *= (1.0f - alpha + 1e-10f);
        acc += wi;
        rgb0 += wi * g_col_c[(r * NCO + s) * 3 + 0];
        rgb1 += wi * g_col_c[(r * NCO + s) * 3 + 1];
        rgb2 += wi * g_col_c[(r * NCO + s) * 3 + 2];
        dsum += wi * cd[s];
    }
    float inv = 1.0f / (acc + 1e-8f);
    out[3072 + r * 3 + 0] = 1.0f - acc + (rgb0 * inv) * acc;
    out[3072 + r * 3 + 1] = 1.0f - acc + (rgb1 * inv) * acc;
    out[3072 + r * 3 + 2] = 1.0f - acc + (rgb2 * inv) * acc;
    out[7168 + r] = dsum * inv;

    float bins[63], cdf[63];
    for (int i = 0; i < 63; i++) bins[i] = 0.5f * (cd[i] + cd[i + 1]);
    float wsum = 0.f;
    for (int i = 0; i < 62; i++) wsum += w[i + 1] + 1e-5f;
    cdf[0] = 0.f;
    float c0 = 0.f;
    for (int i = 0; i < 62; i++) { c0 += (w[i + 1] + 1e-5f) / wsum; cdf[i + 1] = c0; }

    float fd[NFI];
    for (int j = 0; j < NFI; j++) {
        float u = (j + 0.5f) * (1.0f / NFI);
        int ind = 0;
        for (int k = 0; k < 63; k++) if (cdf[k] <= u) ind = k + 1;
        int below = ind - 1; if (below < 0) below = 0; if (below > 62) below = 62;
        int above = ind;     if (above > 62) above = 62;
        float cb = cdf[below], ca = cdf[above];
        float bb = bins[below], ba = bins[above];
        float denom = ca - cb;
        if (denom < 1e-5f) denom = 1.0f;
        fd[j] = bb + (u - cb) / denom * (ba - bb);
        g_fdepths[r * NFI + j] = fd[j];
    }
    // ---- stable merge (coarse-first on ties) with provenance ----
    int i = 0, j = 0;
    for (int k = 0; k < NAGG; k++) {
        if (j >= NFI || (i < NCO && cd[i] <= fd[j])) {
            g_depths[r * NAGG + k] = cd[i];
            g_src[r * NAGG + k] = i;
            i++;
        } else {
            g_depths[r * NAGG + k] = fd[j];
            g_src[r * NAGG + k] = NCO + j;
            j++;
        }
    }
}

// ---------------- fine render: gather dens/col via provenance ----------------
__global__ void fine_post_kernel(float* __restrict__ out) {
    int r = blockIdx.x * blockDim.x + threadIdx.x;
    if (r >= RAYS) return;
    float d[NAGG];
    for (int s = 0; s < NAGG; s++) d[s] = g_depths[r * NAGG + s];
    float T = 1.f, acc = 0.f, rgb0 = 0.f, rgb1 = 0.f, rgb2 = 0.f, dsum = 0.f;
    for (int s = 0; s < NAGG; s++) {
        float seg = (s < NAGG - 1) ? d[s + 1] - d[s] : 1e10f;
        int idx = g_src[r * NAGG + s];
        float dens, cr, cg, cb;
        if (idx < NCO) {
            dens = g_dens_c[r * NCO + idx];
            cr = g_col_c[(r * NCO + idx) * 3 + 0];
            cg = g_col_c[(r * NCO + idx) * 3 + 1];
            cb = g_col_c[(r * NCO + idx) * 3 + 2];
        } else {
            int fi = idx - NCO;
            dens = g_dens_f[r * NFI + fi];
            cr = g_col_f[(r * NFI + fi) * 3 + 0];
            cg = g_col_f[(r * NFI + fi) * 3 + 1];
            cb = g_col_f[(r * NFI + fi) * 3 + 2];
        }
        float alpha = 1.0f - expf(-dens * seg);
        float wi = alpha * T;
        T *= (1.0f - alpha + 1e-10f);
        acc += wi;
        rgb0 += wi * cr;
        rgb1 += wi * cg;
        rgb2 += wi * cb;
        dsum += wi * d[s];
    }
    float inv = 1.0f / (acc + 1e-8f);
    out[r * 3 + 0] = 1.0f - acc + (rgb0 * inv) * acc;
    out[r * 3 + 1] = 1.0f - acc + (rgb1 * inv) * acc;
    out[r * 3 + 2] = 1.0f - acc + (rgb2 * inv) * acc;
    out[6144 + r] = dsum * inv;
}

// ---------------- launch ----------------
extern "C" void kernel_launch(void* const* d_in, const int* in_sizes, int n_in,
                              void* d_out, int out_size) {
    const float* z    = (const float*)d_in[0];
    NetP P;
    P.x    = (const float*)d_in[1];
    P.rays = (const float*)d_in[2];
    const float* ln1w = (const float*)d_in[3];
    const float* ln1b = (const float*)d_in[4];
    const float* wq   = (const float*)d_in[5];
    const float* wkv  = (const float*)d_in[6];
    P.wo   = (const float*)d_in[7];
    P.bo   = (const float*)d_in[8];
    const float* ln2w = (const float*)d_in[9];
    const float* ln2b = (const float*)d_in[10];
    const float* w1   = (const float*)d_in[11];
    const float* b1   = (const float*)d_in[12];
    P.w2   = (const float*)d_in[13];
    P.b2   = (const float*)d_in[14];
    P.wc1  = (const float*)d_in[15];
    P.bc1  = (const float*)d_in[16];
    P.wc2  = (const float*)d_in[17];
    P.bc2  = (const float*)d_in[18];
    P.wd1  = (const float*)d_in[19];
    P.bd1  = (const float*)d_in[20];
    P.wd2  = (const float*)d_in[21];
    P.bd2  = (const float*)d_in[22];
    float* out = (float*)d_out;

    const int FOLD_N = 2 * DD * INNERD + 2 * DD * MLPD;
    kv_kernel<<<(2 * PTOK * 2 * INNERD + 255) / 256, 256>>>(z, wkv);
    fold_scale_kernel<<<(FOLD_N + 255) / 256, 256>>>(ln1w, wq, ln2w, w1);
    fold_uc_kernel<<<(2 * INNERD + 2 * MLPD + 255) / 256, 256>>>(ln1w, ln1b, wq, ln2w, ln2b, w1, b1);
    // coarse network: 1024*64 points
    net_kernel<<<(RAYS * NCO) / PPB, 64>>>(P, 0);
    // coarse render + fine sampling + merge (records provenance)
    coarse_post_kernel<<<(RAYS + 127) / 128, 128>>>(out);
    // fine network: only the 1024*32 NEW sample points
    net_kernel<<<(RAYS * NFI) / PPB, 64>>>(P, 1);
    // fine render (gathers coarse outputs via provenance)
    fine_post_kernel<<<(RAYS + 127) / 128, 128>>>(out);
}

// round 17
// speedup vs baseline: 1.7393x; 1.0026x over previous
#include <cuda_runtime.h>
#include <math.h>

typedef unsigned long long ull;

// ---------------- problem constants ----------------
#define RAYS    1024
#define NCO     64
#define NFI     32
#define NAGG    96
#define MIND    0.035f
#define MAXD    35.0f
#define DD      90
#define NHEADS  12
#define DHD     64
#define INNERD  768
#define MLPD    1536
#define KVD     768
#define PTOK    128
#define LDH     100     // paired row stride 2*LDH=200 (== 8 mod 32 -> conflict-free)
#define LDSS    132     // paired row stride 2*LDSS=264 (== 8 mod 32)
#define PPB     16      // points per block (2 warps x 8 points = 4 pairs/warp)

// ---------------- device scratch ----------------
__device__ float g_kt   [2*NHEADS*DHD*PTOK];   // [layer][head][d][key]
__device__ float g_vv   [2*NHEADS*PTOK*DHD];   // [layer][head][key][d]
__device__ float g_dens_c[RAYS*NCO];
__device__ float g_col_c [RAYS*NCO*3];
__device__ float g_dens_f[RAYS*NFI];           // FINE-ONLY points (32/ray)
__device__ float g_col_f [RAYS*NFI*3];
__device__ float g_depths [RAYS*NAGG];         // merged depths (for rendering)
__device__ float g_fdepths[RAYS*NFI];          // fine sample depths (net input)
__device__ int   g_src    [RAYS*NAGG];         // merge provenance: <NCO coarse idx, else NCO+fine idx
// LN-folded weights: W' = diag(ln_w) @ W ; U = colsum(diag(ln_w)@W) ; C = ln_b @ W (+bias)
__device__ float g_wq2[2*DD*INNERD];
__device__ float g_uq [2*INNERD];
__device__ float g_cq [2*INNERD];
__device__ float g_w12[2*DD*MLPD];
__device__ float g_u1 [2*MLPD];
__device__ float g_c1 [2*MLPD];   // includes b1

struct NetP {
    const float *x, *rays;
    const float *wo, *bo, *w2, *b2;
    const float *wc1, *bc1, *wc2, *bc2, *wd1, *bd1, *wd2, *bd2;
};

__device__ __forceinline__ float coarse_depth(int s) {
    const float step = (MAXD - MIND) / 64.0f;
    return 0.5f * ((MIND + s * step) + (MIND + (s + 1) * step));
}

// ---------------- f32x2 helpers ----------------
__device__ __forceinline__ ull pack2(float x, float y) {
    ull r; asm("mov.b64 %0, {%1, %2};" : "=l"(r) : "f"(x), "f"(y)); return r;
}
__device__ __forceinline__ ull pack2d(float x) { return pack2(x, x); }
__device__ __forceinline__ void ffma2(ull& d, ull a, ull b) {
    asm("fma.rn.f32x2 %0, %1, %2, %0;" : "+l"(d) : "l"(a), "l"(b));
}
__device__ __forceinline__ float2 unpack2(ull v) {
    float2 r; asm("mov.b64 {%0, %1}, %2;" : "=f"(r.x), "=f"(r.y) : "l"(v)); return r;
}

// paired activation layout: buf[(p>>1)*2*LD + 2*k + (p&1)]
#define PIDX(p, LD, k) (((p) >> 1) * (2 * (LD)) + 2 * (k) + ((p) & 1))

// ---------------- KV precompute ----------------
__global__ void kv_kernel(const float* __restrict__ z, const float* __restrict__ wkv) {
    int e = blockIdx.x * blockDim.x + threadIdx.x;
    if (e >= 2 * PTOK * 2 * INNERD) return;
    int layer = e / (PTOK * 2 * INNERD);
    int rem   = e - layer * (PTOK * 2 * INNERD);
    int p   = rem / (2 * INNERD);
    int col = rem - p * (2 * INNERD);
    const float* zr = z + p * KVD;
    const float* wc = wkv + layer * KVD * 2 * INNERD + col;
    float acc = 0.f;
#pragma unroll 8
    for (int k = 0; k < KVD; k++) acc = fmaf(zr[k], wc[k * 2 * INNERD], acc);
    int head = col >> 7, c = col & 127;
    if (c < DHD) g_kt[((layer * NHEADS + head) * DHD + c) * PTOK + p] = acc;
    else         g_vv[((layer * NHEADS + head) * PTOK + p) * DHD + (c - DHD)] = acc;
}

// ---------------- LN-fold precompute ----------------
__global__ void fold_scale_kernel(const float* __restrict__ ln1w, const float* __restrict__ wq,
                                  const float* __restrict__ ln2w, const float* __restrict__ w1) {
    int e = blockIdx.x * blockDim.x + threadIdx.x;
    const int T1 = 2 * DD * INNERD;
    if (e < T1) {
        int layer = e / (DD * INNERD);
        int k = (e - layer * DD * INNERD) / INNERD;
        g_wq2[e] = ln1w[layer * DD + k] * wq[e];
    } else if (e < T1 + 2 * DD * MLPD) {
        int e2 = e - T1;
        int layer = e2 / (DD * MLPD);
        int k = (e2 - layer * DD * MLPD) / MLPD;
        g_w12[e2] = ln2w[layer * DD + k] * w1[e2];
    }
}

__global__ void fold_uc_kernel(const float* __restrict__ ln1w, const float* __restrict__ ln1b,
                               const float* __restrict__ wq,
                               const float* __restrict__ ln2w, const float* __restrict__ ln2b,
                               const float* __restrict__ w1, const float* __restrict__ b1) {
    int e = blockIdx.x * blockDim.x + threadIdx.x;
    if (e < 2 * INNERD) {
        int layer = e / INNERD, o = e - layer * INNERD;
        const float* W = wq + layer * DD * INNERD + o;
        float U = 0.f, C = 0.f;
        for (int k = 0; k < DD; k++) {
            float w = W[k * INNERD];
            U = fmaf(ln1w[layer * DD + k], w, U);
            C = fmaf(ln1b[layer * DD + k], w, C);
        }
        g_uq[e] = U; g_cq[e] = C;
    } else if (e < 2 * INNERD + 2 * MLPD) {
        int e2 = e - 2 * INNERD;
        int layer = e2 / MLPD, o = e2 - layer * MLPD;
        const float* W = w1 + layer * DD * MLPD + o;
        float U = 0.f, C = 0.f;
        for (int k = 0; k < DD; k++) {
            float w = W[k * MLPD];
            U = fmaf(ln2w[layer * DD + k], w, U);
            C = fmaf(ln2b[layer * DD + k], w, C);
        }
        g_u1[e2] = U; g_c1[e2] = C + b1[e2];
    }
}

// ---------------- FFMA2 register-tiled GEMM (simple, R3-best) --------------
// Input is PAIRED smem. Warp owns 4 point-pairs (8 points). Lane owns:
//   WMODE==1 (vector weights): cols NCOL*l + j  (NCOL in {2,4}), NO == 32*NCOL
//   WMODE==0 (strided):        cols l + 32*j, masked at NO
template <int NI, int NCOL, int LDIN, int WMODE, int NO, class Epi>
__device__ __forceinline__ void gemm2(const float* __restrict__ in,
                                      const float* __restrict__ W,
                                      const int ldw, Epi epi) {
    const int l  = threadIdx.x & 31;
    const int wp = threadIdx.x >> 5;
    ull acc[4][NCOL];
#pragma unroll
    for (int i = 0; i < 4; i++)
#pragma unroll
        for (int j = 0; j < NCOL; j++) acc[i][j] = 0ull;

    const float* inb = in + (wp * 4) * (2 * LDIN);
    int ni = 0;
#pragma unroll 2
    for (; ni + 4 <= NI; ni += 4) {
        ull a[4][4];
#pragma unroll
        for (int i = 0; i < 4; i++) {
            ulonglong2 t0 = *reinterpret_cast<const ulonglong2*>(inb + i * 2 * LDIN + 2 * ni);
            ulonglong2 t1 = *reinterpret_cast<const ulonglong2*>(inb + i * 2 * LDIN + 2 * ni + 4);
            a[i][0] = t0.x; a[i][1] = t0.y; a[i][2] = t1.x; a[i][3] = t1.y;
        }
#pragma unroll
        for (int k = 0; k < 4; k++) {
            ull wv[NCOL];
            if (WMODE == 1) {
                if (NCOL == 4) {
                    float4 w4 = *reinterpret_cast<const float4*>(W + (ni + k) * ldw + 4 * l);
                    wv[0] = pack2d(w4.x); wv[1] = pack2d(w4.y);
                    wv[2] = pack2d(w4.z); wv[3] = pack2d(w4.w);
                } else {
                    float2 w2 = *reinterpret_cast<const float2*>(W + (ni + k) * ldw + 2 * l);
                    wv[0] = pack2d(w2.x); wv[1] = pack2d(w2.y);
                }
            } else {
#pragma unroll
                for (int j = 0; j < NCOL; j++) {
                    int o = l + 32 * j;
                    float w = (o < NO) ? W[(ni + k) * ldw + o] : 0.f;
                    wv[j] = pack2d(w);
                }
            }
#pragma unroll
            for (int i = 0; i < 4; i++)
#pragma unroll
                for (int j = 0; j < NCOL; j++) ffma2(acc[i][j], a[i][k], wv[j]);
        }
    }
    if (NI & 2) {   // remainder of 2 (NI=90)
        ull a[4][2];
#pragma unroll
        for (int i = 0; i < 4; i++) {
            ulonglong2 t0 = *reinterpret_cast<const ulonglong2*>(inb + i * 2 * LDIN + 2 * ni);
            a[i][0] = t0.x; a[i][1] = t0.y;
        }
#pragma unroll
        for (int k = 0; k < 2; k++) {
            ull wv[NCOL];
            if (WMODE == 1) {
                if (NCOL == 4) {
                    float4 w4 = *reinterpret_cast<const float4*>(W + (ni + k) * ldw + 4 * l);
                    wv[0] = pack2d(w4.x); wv[1] = pack2d(w4.y);
                    wv[2] = pack2d(w4.z); wv[3] = pack2d(w4.w);
                } else {
                    float2 w2 = *reinterpret_cast<const float2*>(W + (ni + k) * ldw + 2 * l);
                    wv[0] = pack2d(w2.x); wv[1] = pack2d(w2.y);
                }
            } else {
#pragma unroll
                for (int j = 0; j < NCOL; j++) {
                    int o = l + 32 * j;
                    float w = (o < NO) ? W[(ni + k) * ldw + o] : 0.f;
                    wv[j] = pack2d(w);
                }
            }
#pragma unroll
            for (int i = 0; i < 4; i++)
#pragma unroll
                for (int j = 0; j < NCOL; j++) ffma2(acc[i][j], a[i][k], wv[j]);
        }
    }
#pragma unroll
    for (int i = 0; i < 4; i++)
#pragma unroll
        for (int j = 0; j < NCOL; j++) {
            int o = (WMODE == 1) ? (NCOL * l + j) : (l + 32 * j);
            if (WMODE == 1 || o < NO) epi(wp * 4 + i, o, unpack2(acc[i][j]));
        }
}

// Warp-local LN statistics only (mean, rsqrt(var)) -> st[2*pt], st[2*pt+1]
__device__ __forceinline__ void ln_stats(const float* __restrict__ src, float* __restrict__ st) {
    const int l  = threadIdx.x & 31;
    const int wp = threadIdx.x >> 5;
    const int pl = l >> 2, sub = l & 3;
    const int pt = wp * 8 + pl;
    const float* rowb = src + ((pt >> 1) * (2 * LDH) + (pt & 1));
    float s = 0.f;
    for (int f = sub; f < DD; f += 4) s += rowb[2 * f];
    s += __shfl_xor_sync(0xffffffffu, s, 1);
    s += __shfl_xor_sync(0xffffffffu, s, 2);
    float m = s * (1.0f / DD);
    float v = 0.f;
    for (int f = sub; f < DD; f += 4) { float d = rowb[2 * f] - m; v += d * d; }
    v += __shfl_xor_sync(0xffffffffu, v, 1);
    v += __shfl_xor_sync(0xffffffffu, v, 2);
    float inv = 1.0f / sqrtf(v * (1.0f / DD) + 1e-5f);
    if (sub == 0) { st[2 * pt] = m; st[2 * pt + 1] = inv; }
    __syncwarp();
}

// ---------------- fused NeRF network: 16 points / 2-warp block ----------------
// mode 0: coarse (64 samples/ray, analytic depths). mode 1: fine (32 NEW
// samples/ray, depths from g_fdepths). Coarse points of the merged fine set
// are NOT recomputed — the network is pointwise, so their outputs are gathered
// from the coarse pass in fine_post_kernel via g_src.
// __launch_bounds__(64, 8): pin to <=128 regs (8 resident blocks) — measured optimum.
__global__ void __launch_bounds__(64, 8) net_kernel(NetP P, int mode) {
    __shared__ __align__(16) float sh_h [(PPB / 2) * 2 * LDH ];  // 1600
    __shared__ __align__(16) float sh_s [(PPB / 2) * 2 * LDSS];  // 2112
    __shared__ __align__(16) float sh_qo[(PPB / 2) * 2 * DHD ];  // 1024 (coords/q/o aliased)
    __shared__ float sh_st[2 * PPB];   // (m, inv) per point (LN stats)
    __shared__ float sh_ip[PPB];       // 1/sum_exp per point (softmax)

    const int t  = threadIdx.x;
    const int l  = t & 31;
    const int wp = t >> 5;
    const int pl = l >> 2, sub = l & 3;
    const int base = blockIdx.x * PPB;
    const int S = mode ? NFI : NCO;

    // ---- coords (temp in sh_qo, consumed by posenc) ----
    if (l < 24) {
        int p = l / 3, d = l - (l / 3) * 3;
        int gp = base + wp * 8 + p;
        int r = gp / S, s = gp - r * S;
        float depth = mode ? g_fdepths[r * NFI + s] : coarse_depth(s);
        sh_qo[(wp * 8 + p) * 4 + d] = P.x[r * 3 + d] + P.rays[r * 3 + d] * depth;
    }
    __syncwarp();
    // ---- positional encoding ----
    for (int idx = l; idx < 8 * DD; idx += 32) {
        int p = idx / DD, f = idx - p * DD;
        int bb = (f < 45) ? f : f - 45;
        int dim = bb / 15, oct = bb - dim * 15;
        int pt = wp * 8 + p;
        float arg = sh_qo[pt * 4 + dim] * (3.14159265358979323846f * (float)(1 << oct));
        sh_h[PIDX(pt, LDH, f)] = (f < 45) ? sinf(arg) : cosf(arg);
    }
    __syncwarp();

    for (int layer = 0; layer < 2; layer++) {
        // ---- LN1 stats + attention (LN folded into wq via g_wq2/g_uq/g_cq) ----
        ln_stats(sh_h, sh_st);
        {
            float m_[8], iv_[8];
#pragma unroll
            for (int k = 0; k < 8; k++) {
                m_[k]  = sh_st[2 * (wp * 8 + k)];
                iv_[k] = sh_st[2 * (wp * 8 + k) + 1];
            }
            float2 accw[4][3];
#pragma unroll
            for (int i = 0; i < 4; i++)
#pragma unroll
                for (int j = 0; j < 3; j++) accw[i][j] = make_float2(0.f, 0.f);
            for (int head = 0; head < NHEADS; head++) {
                const float* Uq = g_uq + layer * INNERD + head * DHD;
                const float* Cq = g_cq + layer * INNERD + head * DHD;
                gemm2<DD, 2, LDH, 1, DHD>(sh_h, g_wq2 + layer * DD * INNERD + head * DHD, INNERD,
                    [&](int pr, int o, float2 v) {
                        float U = Uq[o], C = Cq[o];
                        int i2 = (pr & 3) * 2;
                        v.x = iv_[i2]     * (v.x - m_[i2]     * U) + C;
                        v.y = iv_[i2 + 1] * (v.y - m_[i2 + 1] * U) + C;
                        *reinterpret_cast<float2*>(&sh_qo[pr * 2 * DHD + 2 * o]) = v;
                    });
                __syncwarp();
                gemm2<DHD, 4, DHD, 1, PTOK>(sh_qo, g_kt + (layer * NHEADS + head) * DHD * PTOK, PTOK,
                    [&](int pr, int o, float2 v) {
                        v.x *= 0.125f; v.y *= 0.125f;
                        *reinterpret_cast<float2*>(&sh_s[pr * 2 * LDSS + 2 * o]) = v;
                    });
                __syncwarp();
                // ---- softmax over 128 keys: 4 lanes / point; stores UNNORMALIZED
                // exp, 1/sum folded into att.V epilogue ----
                {
                    const int pt = wp * 8 + pl;
                    float* rowb = sh_s + ((pt >> 1) * 2 * LDSS + (pt & 1));
                    float mx = rowb[2 * sub];
#pragma unroll
                    for (int k = 1; k < 32; k++) mx = fmaxf(mx, rowb[2 * (sub + 4 * k)]);
                    mx = fmaxf(mx, __shfl_xor_sync(0xffffffffu, mx, 1));
                    mx = fmaxf(mx, __shfl_xor_sync(0xffffffffu, mx, 2));
                    float ps = 0.f;
#pragma unroll
                    for (int k = 0; k < 32; k++) {
                        float v = __expf(rowb[2 * (sub + 4 * k)] - mx);
                        rowb[2 * (sub + 4 * k)] = v;
                        ps += v;
                    }
                    ps += __shfl_xor_sync(0xffffffffu, ps, 1);
                    ps += __shfl_xor_sync(0xffffffffu, ps, 2);
                    if (sub == 0) sh_ip[pt] = 1.0f / ps;
                }
                __syncwarp();
                gemm2<PTOK, 2, LDSS, 1, DHD>(sh_s, g_vv + (layer * NHEADS + head) * PTOK * DHD, DHD,
                    [&](int pr, int o, float2 v) {
                        v.x *= sh_ip[2 * pr];
                        v.y *= sh_ip[2 * pr + 1];
                        *reinterpret_cast<float2*>(&sh_qo[pr * 2 * DHD + 2 * o]) = v;
                    });
                __syncwarp();
                gemm2<DHD, 3, DHD, 0, DD>(sh_qo, P.wo + layer * INNERD * DD + head * DHD * DD, DD,
                    [&](int pr, int o, float2 v) {
                        int j = o >> 5, i = pr & 3;
                        accw[i][j].x += v.x; accw[i][j].y += v.y;
                    });
                __syncwarp();
            }
            const float* bo = P.bo + layer * DD;
#pragma unroll
            for (int i = 0; i < 4; i++)
#pragma unroll
                for (int j = 0; j < 3; j++) {
                    int o = l + 32 * j;
                    if (o < DD) {
                        int pr = wp * 4 + i;
                        float2* addr = reinterpret_cast<float2*>(&sh_h[pr * 2 * LDH + 2 * o]);
                        float2 h = *addr;
                        float bb = bo[o];
                        h.x += accw[i][j].x + bb;
                        h.y += accw[i][j].y + bb;
                        *addr = h;
                    }
                }
            __syncwarp();
        }
        // ---- LN2 stats + MLP (LN folded into w1 via g_w12/g_u1/g_c1) ----
        ln_stats(sh_h, sh_st);
        {
            float m_[8], iv_[8];
#pragma unroll
            for (int k = 0; k < 8; k++) {
                m_[k]  = sh_st[2 * (wp * 8 + k)];
                iv_[k] = sh_st[2 * (wp * 8 + k) + 1];
            }
            float2 accm[4][3];
#pragma unroll
            for (int i = 0; i < 4; i++)
#pragma unroll
                for (int j = 0; j < 3; j++) accm[i][j] = make_float2(0.f, 0.f);
            for (int c = 0; c < MLPD / 128; c++) {
                const float* U1 = g_u1 + layer * MLPD + c * 128;
                const float* C1 = g_c1 + layer * MLPD + c * 128;
                gemm2<DD, 4, LDH, 1, 128>(sh_h, g_w12 + layer * DD * MLPD + c * 128, MLPD,
                    [&](int pr, int o, float2 v) {
                        float U = U1[o], C = C1[o];
                        int i2 = (pr & 3) * 2;
                        float x0 = iv_[i2]     * (v.x - m_[i2]     * U) + C;
                        float x1 = iv_[i2 + 1] * (v.y - m_[i2 + 1] * U) + C;
                        v.x = 0.5f * x0 * (1.0f + erff(x0 * 0.70710678118654752f));
                        v.y = 0.5f * x1 * (1.0f + erff(x1 * 0.70710678118654752f));
                        *reinterpret_cast<float2*>(&sh_s[pr * 2 * LDSS + 2 * o]) = v;
                    });
                __syncwarp();
                gemm2<128, 3, LDSS, 0, DD>(sh_s, P.w2 + layer * MLPD * DD + c * 128 * DD, DD,
                    [&](int pr, int o, float2 v) {
                        int j = o >> 5, i = pr & 3;
                        accm[i][j].x += v.x; accm[i][j].y += v.y;
                    });
                __syncwarp();
            }
            const float* b2 = P.b2 + layer * DD;
#pragma unroll
            for (int i = 0; i < 4; i++)
#pragma unroll
                for (int j = 0; j < 3; j++) {
                    int o = l + 32 * j;
                    if (o < DD) {
                        int pr = wp * 4 + i;
                        float2* addr = reinterpret_cast<float2*>(&sh_h[pr * 2 * LDH + 2 * o]);
                        float2 h = *addr;
                        float bb = b2[o];
                        h.x += accm[i][j].x + bb;
                        h.y += accm[i][j].y + bb;
                        *addr = h;
                    }
                }
            __syncwarp();
        }
    }

    // ---- density head ----
    gemm2<DD, 4, LDH, 1, 128>(sh_h, P.wd1, 128,
        [&](int pr, int o, float2 v) {
            float bb = P.bd1[o];
            v.x = fmaxf(v.x + bb, 0.f); v.y = fmaxf(v.y + bb, 0.f);
            *reinterpret_cast<float2*>(&sh_s[pr * 2 * LDSS + 2 * o]) = v;
        });
    __syncwarp();
    {
        const int pt = wp * 8 + pl;
        const float* rowb = sh_s + ((pt >> 1) * 2 * LDSS + (pt & 1));
        float a = 0.f;
#pragma unroll
        for (int k = 0; k < 32; k++) a = fmaf(rowb[2 * (sub + 4 * k)], P.wd2[sub + 4 * k], a);
        a += __shfl_xor_sync(0xffffffffu, a, 1);
        a += __shfl_xor_sync(0xffffffffu, a, 2);
        if (sub == 0) {
            a += P.bd2[0];
            float sp = fmaxf(a, 0.f) + log1pf(__expf(-fabsf(a)));
            float* dst = mode ? g_dens_f : g_dens_c;
            dst[base + pt] = sp;
        }
    }
    __syncwarp();
    // ---- color head ----
    gemm2<DD, 4, LDH, 1, 128>(sh_h, P.wc1, 128,
        [&](int pr, int o, float2 v) {
            float bb = P.bc1[o];
            v.x = fmaxf(v.x + bb, 0.f); v.y = fmaxf(v.y + bb, 0.f);
            *reinterpret_cast<float2*>(&sh_s[pr * 2 * LDSS + 2 * o]) = v;
        });
    __syncwarp();
    {
        const int pt = wp * 8 + pl;
        const float* rowb = sh_s + ((pt >> 1) * 2 * LDSS + (pt & 1));
        float c0 = 0.f, c1 = 0.f, c2 = 0.f;
#pragma unroll
        for (int k = 0; k < 32; k++) {
            float v = rowb[2 * (sub + 4 * k)];
            const float* wr = P.wc2 + (sub + 4 * k) * 3;
            c0 = fmaf(v, wr[0], c0);
            c1 = fmaf(v, wr[1], c1);
            c2 = fmaf(v, wr[2], c2);
        }
        c0 += __shfl_xor_sync(0xffffffffu, c0, 1);
        c0 += __shfl_xor_sync(0xffffffffu, c0, 2);
        c1 += __shfl_xor_sync(0xffffffffu, c1, 1);
        c1 += __shfl_xor_sync(0xffffffffu, c1, 2);
        c2 += __shfl_xor_sync(0xffffffffu, c2, 1);
        c2 += __shfl_xor_sync(0xffffffffu, c2, 2);
        if (sub == 0) {
            int gp = base + pt;
            float* dst = mode ? g_col_f : g_col_c;
            dst[gp * 3 + 0] = 1.0f / (1.0f + __expf(-(c0 + P.bc2[0])));
            dst[gp * 3 + 1] = 1.0f / (1.0f + __expf(-(c1 + P.bc2[1])));
            dst[gp * 3 + 2] = 1.0f / (1.0f + __expf(-(c2 + P.bc2[2])));
        }
    }
}

// ---------------- coarse render + PDF resampling + merge (with provenance) ---
__global__ void coarse_post_kernel(float* __restrict__ out) {
    int r = blockIdx.x * blockDim.x + threadIdx.x;
    if (r >= RAYS) return;
    float cd[NCO];
    for (int s = 0; s < NCO; s++) cd[s] = coarse_depth(s);

    float w[NCO];
    float T = 1.f, acc = 0.f, rgb0 = 0.f, rgb1 = 0.f, rgb2 = 0.f, dsum = 0.f;
    for (int s = 0; s < NCO; s++) {
        float seg = (s < NCO - 1) ? cd[s + 1] - cd[s] : 1e10f;
        float dens = g_dens_c[r * NCO + s];
        float alpha = 1.0f - expf(-dens * seg);
        float wi = alpha * T;
        w[s] = wi;
        T *= (1.0f - alpha + 1e-10f);
        acc += wi;
        rgb0 += wi * g_col_c[(r * NCO + s) * 3 + 0];
        rgb1 += wi * g_col_c[(r * NCO + s) * 3 + 1];
        rgb2 += wi * g_col_c[(r * NCO + s) * 3 + 2];
        dsum += wi * cd[s];
    }
    float inv = 1.0f / (acc + 1e-8f);
    out[3072 + r * 3 + 0] = 1.0f - acc + (rgb0 * inv) * acc;
    out[3072 + r * 3 + 1] = 1.0f - acc + (rgb1 * inv) * acc;
    out[3072 + r * 3 + 2] = 1.0f - acc + (rgb2 * inv) * acc;
    out[7168 + r] = dsum * inv;

    float bins[63], cdf[63];
    for (int i = 0; i < 63; i++) bins[i] = 0.5f * (cd[i] + cd[i + 1]);
    float wsum = 0.f;
    for (int i = 0; i < 62; i++) wsum += w[i + 1] + 1e-5f;
    cdf[0] = 0.f;
    float c0 = 0.f;
    for (int i = 0; i < 62; i++) { c0 += (w[i + 1] + 1e-5f) / wsum; cdf[i + 1] = c0; }

    float fd[NFI];
    for (int j = 0; j < NFI; j++) {
        float u = (j + 0.5f) * (1.0f / NFI);
        int ind = 0;
        for (int k = 0; k < 63; k++) if (cdf[k] <= u) ind = k + 1;
        int below = ind - 1; if (below < 0) below = 0; if (below > 62) below = 62;
        int above = ind;     if (above > 62) above = 62;
        float cb = cdf[below], ca = cdf[above];
        float bb = bins[below], ba = bins[above];
        float denom = ca - cb;
        if (denom < 1e-5f) denom = 1.0f;
        fd[j] = bb + (u - cb) / denom * (ba - bb);
        g_fdepths[r * NFI + j] = fd[j];
    }
    // ---- stable merge (coarse-first on ties) with provenance ----
    int i = 0, j = 0;
    for (int k = 0; k < NAGG; k++) {
        if (j >= NFI || (i < NCO && cd[i] <= fd[j])) {
            g_depths[r * NAGG + k] = cd[i];
            g_src[r * NAGG + k] = i;
            i++;
        } else {
            g_depths[r * NAGG + k] = fd[j];
            g_src[r * NAGG + k] = NCO + j;
            j++;
        }
    }
}

// ---------------- fine render: gather dens/col via provenance ----------------
__global__ void fine_post_kernel(float* __restrict__ out) {
    int r = blockIdx.x * blockDim.x + threadIdx.x;
    if (r >= RAYS) return;
    float d[NAGG];
    for (int s = 0; s < NAGG; s++) d[s] = g_depths[r * NAGG + s];
    float T = 1.f, acc = 0.f, rgb0 = 0.f, rgb1 = 0.f, rgb2 = 0.f, dsum = 0.f;
    for (int s = 0; s < NAGG; s++) {
        float seg = (s < NAGG - 1) ? d[s + 1] - d[s] : 1e10f;
        int idx = g_src[r * NAGG + s];
        float dens, cr, cg, cb;
        if (idx < NCO) {
            dens = g_dens_c[r * NCO + idx];
            cr = g_col_c[(r * NCO + idx) * 3 + 0];
            cg = g_col_c[(r * NCO + idx) * 3 + 1];
            cb = g_col_c[(r * NCO + idx) * 3 + 2];
        } else {
            int fi = idx - NCO;
            dens = g_dens_f[r * NFI + fi];
            cr = g_col_f[(r * NFI + fi) * 3 + 0];
            cg = g_col_f[(r * NFI + fi) * 3 + 1];
            cb = g_col_f[(r * NFI + fi) * 3 + 2];
        }
        float alpha = 1.0f - expf(-dens * seg);
        float wi = alpha * T;
        T *= (1.0f - alpha + 1e-10f);
        acc += wi;
        rgb0 += wi * cr;
        rgb1 += wi * cg;
        rgb2 += wi * cb;
        dsum += wi * d[s];
    }
    float inv = 1.0f / (acc + 1e-8f);
    out[r * 3 + 0] = 1.0f - acc + (rgb0 * inv) * acc;
    out[r * 3 + 1] = 1.0f - acc + (rgb1 * inv) * acc;
    out[r * 3 + 2] = 1.0f - acc + (rgb2 * inv) * acc;
    out[6144 + r] = dsum * inv;
}

// ---------------- launch ----------------
extern "C" void kernel_launch(void* const* d_in, const int* in_sizes, int n_in,
                              void* d_out, int out_size) {
    const float* z    = (const float*)d_in[0];
    NetP P;
    P.x    = (const float*)d_in[1];
    P.rays = (const float*)d_in[2];
    const float* ln1w = (const float*)d_in[3];
    const float* ln1b = (const float*)d_in[4];
    const float* wq   = (const float*)d_in[5];
    const float* wkv  = (const float*)d_in[6];
    P.wo   = (const float*)d_in[7];
    P.bo   = (const float*)d_in[8];
    const float* ln2w = (const float*)d_in[9];
    const float* ln2b = (const float*)d_in[10];
    const float* w1   = (const float*)d_in[11];
    const float* b1   = (const float*)d_in[12];
    P.w2   = (const float*)d_in[13];
    P.b2   = (const float*)d_in[14];
    P.wc1  = (const float*)d_in[15];
    P.bc1  = (const float*)d_in[16];
    P.wc2  = (const float*)d_in[17];
    P.bc2  = (const float*)d_in[18];
    P.wd1  = (const float*)d_in[19];
    P.bd1  = (const float*)d_in[20];
    P.wd2  = (const float*)d_in[21];
    P.bd2  = (const float*)d_in[22];
    float* out = (float*)d_out;

    const int FOLD_N = 2 * DD * INNERD + 2 * DD * MLPD;
    kv_kernel<<<(2 * PTOK * 2 * INNERD + 255) / 256, 256>>>(z, wkv);
    fold_scale_kernel<<<(FOLD_N + 255) / 256, 256>>>(ln1w, wq, ln2w, w1);
    fold_uc_kernel<<<(2 * INNERD + 2 * MLPD + 255) / 256, 256>>>(ln1w, ln1b, wq, ln2w, ln2b, w1, b1);
    // coarse network: 1024*64 points
    net_kernel<<<(RAYS * NCO) / PPB, 64>>>(P, 0);
    // coarse render + fine sampling + merge (records provenance)
    coarse_post_kernel<<<(RAYS + 127) / 128, 128>>>(out);
    // fine network: only the 1024*32 NEW sample points
    net_kernel<<<(RAYS * NFI) / PPB, 64>>>(P, 1);
    // fine render (gathers coarse outputs via provenance)
    fine_post_kernel<<<(RAYS + 127) / 128, 128>>>(out);
}